// round 2
// baseline (speedup 1.0000x reference)
#include <cuda_runtime.h>
#include <math.h>

typedef unsigned long long ull;

#define NN      100000
#define EE      128
#define A_AT    150000
#define A_CL    150000
#define A_ON    150000
#define TROWS   750000          // 300000 (at) + 150000 (clear) + 300000 (on)
#define SMOOTHF 12.0f

// ---------------- scratch (static device globals; no allocations) ----------------
__device__ float    g_x[(size_t)A_AT * 256];        // gathered inputs (reused per relation)
__device__ float    g_hidden[(size_t)A_AT * 256];   // relation-MLP hidden
__device__ float    g_msg[(size_t)TROWS * 128];     // all messages, concat [at|clear|on]
__device__ unsigned g_smaxu[(size_t)NN * 128];      // encoded segment max
__device__ float    g_smax[(size_t)NN * 128];       // decoded + clamped segment max
__device__ float    g_sum[(size_t)NN * 128];        // segment sum of exps
__device__ float    g_updin[(size_t)NN * 256];      // [max_msg, h]
__device__ float    g_t[(size_t)NN * 256];          // update-MLP hidden

// ---------------- helpers ----------------
__device__ __forceinline__ void fma2(ull &d, ull a, ull b) {
    asm("fma.rn.f32x2 %0, %1, %2, %3;" : "=l"(d) : "l"(a), "l"(b), "l"(d));
}
__device__ __forceinline__ void unpack2(ull v, float &lo, float &hi) {
    asm("mov.b64 {%0,%1}, %2;" : "=f"(lo), "=f"(hi) : "l"(v));
}
__device__ __forceinline__ float mish_f(float x) {
    float sp = (x > 20.f) ? x : log1pf(expf(x));
    return x * tanhf(sp);
}
// order-preserving float<->uint encoding for atomicMax over signed floats
__device__ __forceinline__ unsigned encf(float f) {
    unsigned u = __float_as_uint(f);
    return (u & 0x80000000u) ? ~u : (u | 0x80000000u);
}
__device__ __forceinline__ float decf(unsigned u) {
    return (u & 0x80000000u) ? __uint_as_float(u & 0x7FFFFFFFu)
                             : __uint_as_float(~u);
}

// ---------------- GEMM: C[M,N] = epilogue(A[M,K] @ B[K,N] + bias) ----------------
// MODE 0: C = mish(acc + bias)
// MODE 1: C = X + acc + bias        (X same shape as C; X==C in-place is safe)
#define BMx 128
#define BNx 128
#define BKx 16
#define AD_STRIDE 258   // 2*BMx + 2: chosen so the 4 k-rows touched by a lane-quad hit distinct banks

template<int MODE>
__global__ void __launch_bounds__(256, 2) gemm_f32(
    const float* __restrict__ A, const float* __restrict__ B,
    const float* __restrict__ bias, const float* __restrict__ X,
    float* __restrict__ C, int M, int N, int K)
{
    extern __shared__ float smem[];
    float (*Ad)[BKx][AD_STRIDE] = (float (*)[BKx][AD_STRIDE])smem;               // duplicated A: [k][2m],[k][2m+1]
    float (*Bs)[BKx][BNx]       = (float (*)[BKx][BNx])(smem + 2 * BKx * AD_STRIDE);

    const int tid  = threadIdx.x;
    const int ty   = tid >> 4;       // 0..15 -> rows ty*8..+7
    const int tx   = tid & 15;       // 0..15 -> cols tx*4..+3 and 64+tx*4..+3
    const int row0 = blockIdx.y * BMx;
    const int col0 = blockIdx.x * BNx;
    const int nkt  = K >> 4;

    ull acc[8][4];
#pragma unroll
    for (int i = 0; i < 8; i++)
#pragma unroll
        for (int j = 0; j < 4; j++) acc[i][j] = 0ull;

    float4 ra[2], rb[2];

    auto loadTiles = [&](int kt) {
#pragma unroll
        for (int s = 0; s < 2; s++) {
            int id   = tid + s * 256;
            int arow = id >> 2, ac = (id & 3) << 2;
            int gr   = row0 + arow;
            ra[s] = (gr < M) ? *(const float4*)(A + (size_t)gr * K + kt * BKx + ac)
                             : make_float4(0.f, 0.f, 0.f, 0.f);
            int brow = id >> 5, bc = (id & 31) << 2;
            rb[s] = *(const float4*)(B + (size_t)(kt * BKx + brow) * N + col0 + bc);
        }
    };
    auto storeTiles = [&](int buf) {
#pragma unroll
        for (int s = 0; s < 2; s++) {
            int id   = tid + s * 256;
            int arow = id >> 2, k0 = (id & 3) << 2;
            float4 v = ra[s];
            float2 d;
            d.x = d.y = v.x; *(float2*)&Ad[buf][k0 + 0][2 * arow] = d;
            d.x = d.y = v.y; *(float2*)&Ad[buf][k0 + 1][2 * arow] = d;
            d.x = d.y = v.z; *(float2*)&Ad[buf][k0 + 2][2 * arow] = d;
            d.x = d.y = v.w; *(float2*)&Ad[buf][k0 + 3][2 * arow] = d;
            int brow = id >> 5, bc = (id & 31) << 2;
            *(float4*)&Bs[buf][brow][bc] = rb[s];
        }
    };

    loadTiles(0);
    storeTiles(0);
    __syncthreads();

    for (int kt = 0; kt < nkt; kt++) {
        int buf = kt & 1;
        if (kt + 1 < nkt) loadTiles(kt + 1);
#pragma unroll
        for (int kk = 0; kk < BKx; kk++) {
            ull a2[8], b2[4];
#pragma unroll
            for (int i = 0; i < 8; i++)
                a2[i] = *(const ull*)&Ad[buf][kk][2 * (ty * 8 + i)];
            ulonglong2 t0 = *(const ulonglong2*)&Bs[buf][kk][tx * 4];
            ulonglong2 t1 = *(const ulonglong2*)&Bs[buf][kk][64 + tx * 4];
            b2[0] = t0.x; b2[1] = t0.y; b2[2] = t1.x; b2[3] = t1.y;
#pragma unroll
            for (int i = 0; i < 8; i++) {
                fma2(acc[i][0], a2[i], b2[0]);
                fma2(acc[i][1], a2[i], b2[1]);
                fma2(acc[i][2], a2[i], b2[2]);
                fma2(acc[i][3], a2[i], b2[3]);
            }
        }
        if (kt + 1 < nkt) storeTiles(buf ^ 1);
        __syncthreads();
    }

    // epilogue
    float bb[8];
#pragma unroll
    for (int j = 0; j < 4; j++) {
        bb[j]     = bias[col0 + tx * 4 + j];
        bb[4 + j] = bias[col0 + 64 + tx * 4 + j];
    }
#pragma unroll
    for (int i = 0; i < 8; i++) {
        int r = row0 + ty * 8 + i;
        if (r >= M) break;
        size_t base0 = (size_t)r * N + col0 + tx * 4;
        size_t base1 = base0 + 64;
        float v[8];
        unpack2(acc[i][0], v[0], v[1]);
        unpack2(acc[i][1], v[2], v[3]);
        unpack2(acc[i][2], v[4], v[5]);
        unpack2(acc[i][3], v[6], v[7]);
#pragma unroll
        for (int q = 0; q < 8; q++) v[q] += bb[q];
        if (MODE == 0) {
#pragma unroll
            for (int q = 0; q < 8; q++) v[q] = mish_f(v[q]);
        } else {
            float4 x0 = *(const float4*)(X + base0);
            float4 x1 = *(const float4*)(X + base1);
            v[0] += x0.x; v[1] += x0.y; v[2] += x0.z; v[3] += x0.w;
            v[4] += x1.x; v[5] += x1.y; v[6] += x1.z; v[7] += x1.w;
        }
        *(float4*)(C + base0) = make_float4(v[0], v[1], v[2], v[3]);
        *(float4*)(C + base1) = make_float4(v[4], v[5], v[6], v[7]);
    }
}

// ---------------- elementwise / aggregation kernels ----------------

// x[seg, 0:128] = h[av[seg], 0:128]   (x flattened [A*ar, 128] == [A, ar*128])
__global__ void gather_kernel(const float* __restrict__ h, const int* __restrict__ av,
                              float* __restrict__ x, long long nseg)
{
    long long i = (long long)blockIdx.x * blockDim.x + threadIdx.x;
    if (i >= nseg * 32) return;
    long long seg = i >> 5;
    int f4 = (int)(i & 31) * 4;
    int node = __ldg(av + seg);
    *(float4*)(x + seg * 128 + f4) = *(const float4*)(h + (size_t)node * 128 + f4);
}

__device__ __forceinline__ int row_to_node(long long row,
                                           const int* __restrict__ at,
                                           const int* __restrict__ cl,
                                           const int* __restrict__ on)
{
    if (row < 300000) return __ldg(at + row);
    if (row < 450000) return __ldg(cl + row - 300000);
    return __ldg(on + row - 450000);
}

__global__ void segmax_kernel(const float* __restrict__ msg,
                              const int* __restrict__ at, const int* __restrict__ cl,
                              const int* __restrict__ on, unsigned* __restrict__ smax)
{
    long long i = (long long)blockIdx.x * blockDim.x + threadIdx.x;
    if (i >= (long long)TROWS * 32) return;
    long long row = i >> 5;
    int f4 = (int)(i & 31) * 4;
    int node = row_to_node(row, at, cl, on);
    float4 v = *(const float4*)(msg + row * 128 + f4);
    unsigned* p = smax + (size_t)node * 128 + f4;
    atomicMax(p + 0, encf(v.x));
    atomicMax(p + 1, encf(v.y));
    atomicMax(p + 2, encf(v.z));
    atomicMax(p + 3, encf(v.w));
}

__global__ void decode_kernel(const unsigned* __restrict__ smaxu, float* __restrict__ smax,
                              float* __restrict__ sum, long long n)
{
    long long i = (long long)blockIdx.x * blockDim.x + threadIdx.x;
    if (i >= n) return;
    unsigned u = smaxu[i];
    smax[i] = (u == 0u) ? 0.f : decf(u);   // empty segment (-inf) -> 0, matching reference
    sum[i]  = 0.f;
}

__global__ void expsum_kernel(const float* __restrict__ msg,
                              const int* __restrict__ at, const int* __restrict__ cl,
                              const int* __restrict__ on, const float* __restrict__ smax,
                              float* __restrict__ sum)
{
    long long i = (long long)blockIdx.x * blockDim.x + threadIdx.x;
    if (i >= (long long)TROWS * 32) return;
    long long row = i >> 5;
    int f4 = (int)(i & 31) * 4;
    int node = row_to_node(row, at, cl, on);
    float4 v = *(const float4*)(msg + row * 128 + f4);
    const float4 m = *(const float4*)(smax + (size_t)node * 128 + f4);
    float* p = sum + (size_t)node * 128 + f4;
    atomicAdd(p + 0, expf(SMOOTHF * (v.x - m.x)));
    atomicAdd(p + 1, expf(SMOOTHF * (v.y - m.y)));
    atomicAdd(p + 2, expf(SMOOTHF * (v.z - m.z)));
    atomicAdd(p + 3, expf(SMOOTHF * (v.w - m.w)));
}

__global__ void updin_kernel(const float* __restrict__ sum, const float* __restrict__ smax,
                             const float* __restrict__ h, float* __restrict__ updin)
{
    long long i = (long long)blockIdx.x * blockDim.x + threadIdx.x;
    if (i >= (long long)NN * 128) return;
    long long node = i >> 7;
    int e = (int)(i & 127);
    float mm = logf(sum[i] + 1e-16f) / SMOOTHF + smax[i];
    updin[node * 256 + e]       = mm;
    updin[node * 256 + 128 + e] = h[i];
}

// ---------------- host launch ----------------
extern "C" void kernel_launch(void* const* d_in, const int* in_sizes, int n_in,
                              void* d_out, int out_size)
{
    const float *emb, *w_in[3], *b_in[3], *w_out[3], *b_out[3], *wui, *bui, *wuo, *buo;
    const int *at, *cl, *on;

    if (in_sizes[2] == 65536) {
        // setup_inputs dict order: emb, [atoms,w_in,b_in,w_out,b_out] x {at,clear,on}, update
        emb = (const float*)d_in[0];
        at  = (const int*)d_in[1];
        w_in[0] = (const float*)d_in[2];  b_in[0] = (const float*)d_in[3];
        w_out[0] = (const float*)d_in[4]; b_out[0] = (const float*)d_in[5];
        cl  = (const int*)d_in[6];
        w_in[1] = (const float*)d_in[7];  b_in[1] = (const float*)d_in[8];
        w_out[1] = (const float*)d_in[9]; b_out[1] = (const float*)d_in[10];
        on  = (const int*)d_in[11];
        w_in[2] = (const float*)d_in[12];  b_in[2] = (const float*)d_in[13];
        w_out[2] = (const float*)d_in[14]; b_out[2] = (const float*)d_in[15];
        wui = (const float*)d_in[16]; bui = (const float*)d_in[17];
        wuo = (const float*)d_in[18]; buo = (const float*)d_in[19];
    } else {
        // reference signature order: emb, atoms_at, atoms_clear, atoms_on, params...
        emb = (const float*)d_in[0];
        at  = (const int*)d_in[1];
        cl  = (const int*)d_in[2];
        on  = (const int*)d_in[3];
        w_in[0] = (const float*)d_in[4];  b_in[0] = (const float*)d_in[5];
        w_out[0] = (const float*)d_in[6]; b_out[0] = (const float*)d_in[7];
        w_in[1] = (const float*)d_in[8];  b_in[1] = (const float*)d_in[9];
        w_out[1] = (const float*)d_in[10]; b_out[1] = (const float*)d_in[11];
        w_in[2] = (const float*)d_in[12];  b_in[2] = (const float*)d_in[13];
        w_out[2] = (const float*)d_in[14]; b_out[2] = (const float*)d_in[15];
        wui = (const float*)d_in[16]; bui = (const float*)d_in[17];
        wuo = (const float*)d_in[18]; buo = (const float*)d_in[19];
    }

    float* h = (float*)d_out;
    float *x, *hid, *msg, *smaxf, *sum, *updin, *t;
    unsigned* smaxu;
    cudaGetSymbolAddress((void**)&x, g_x);
    cudaGetSymbolAddress((void**)&hid, g_hidden);
    cudaGetSymbolAddress((void**)&msg, g_msg);
    cudaGetSymbolAddress((void**)&smaxu, g_smaxu);
    cudaGetSymbolAddress((void**)&smaxf, g_smax);
    cudaGetSymbolAddress((void**)&sum, g_sum);
    cudaGetSymbolAddress((void**)&updin, g_updin);
    cudaGetSymbolAddress((void**)&t, g_t);

    const int smem_bytes = (2 * BKx * AD_STRIDE + 2 * BKx * BNx) * 4;  // 49408
    cudaFuncSetAttribute(gemm_f32<0>, cudaFuncAttributeMaxDynamicSharedMemorySize, smem_bytes);
    cudaFuncSetAttribute(gemm_f32<1>, cudaFuncAttributeMaxDynamicSharedMemorySize, smem_bytes);

    // h <- node_embeddings
    cudaMemcpyAsync(h, emb, (size_t)NN * 128 * sizeof(float), cudaMemcpyDeviceToDevice);

    const dim3 gA(2, (A_AT + BMx - 1) / BMx);   // at/on GEMMs: N=256
    const dim3 gC(1, (A_CL + BMx - 1) / BMx);   // clear GEMMs: N=128
    const dim3 gU2(2, (NN + BMx - 1) / BMx);    // update GEMM1: N=256
    const dim3 gU1(1, (NN + BMx - 1) / BMx);    // update GEMM2: N=128

    for (int layer = 0; layer < 4; layer++) {
        // --- relation "at" (ar=2, d=256), msg rows [0, 300000) ---
        gather_kernel<<<(int)((300000LL * 32 + 255) / 256), 256>>>(h, at, x, 300000);
        gemm_f32<0><<<gA, 256, smem_bytes>>>(x, w_in[0], b_in[0], nullptr, hid, A_AT, 256, 256);
        gemm_f32<1><<<gA, 256, smem_bytes>>>(hid, w_out[0], b_out[0], x, msg, A_AT, 256, 256);

        // --- relation "clear" (ar=1, d=128), msg rows [300000, 450000) ---
        gather_kernel<<<(int)((150000LL * 32 + 255) / 256), 256>>>(h, cl, x, 150000);
        gemm_f32<0><<<gC, 256, smem_bytes>>>(x, w_in[1], b_in[1], nullptr, hid, A_CL, 128, 128);
        gemm_f32<1><<<gC, 256, smem_bytes>>>(hid, w_out[1], b_out[1], x,
                                             msg + (size_t)300000 * 128, A_CL, 128, 128);

        // --- relation "on" (ar=2, d=256), msg rows [450000, 750000) ---
        gather_kernel<<<(int)((300000LL * 32 + 255) / 256), 256>>>(h, on, x, 300000);
        gemm_f32<0><<<gA, 256, smem_bytes>>>(x, w_in[2], b_in[2], nullptr, hid, A_ON, 256, 256);
        gemm_f32<1><<<gA, 256, smem_bytes>>>(hid, w_out[2], b_out[2], x,
                                             msg + (size_t)450000 * 128, A_ON, 256, 256);

        // --- smooth-max aggregation ---
        cudaMemsetAsync(smaxu, 0, (size_t)NN * 128 * sizeof(unsigned));
        segmax_kernel<<<(int)(((long long)TROWS * 32 + 255) / 256), 256>>>(msg, at, cl, on, smaxu);
        decode_kernel<<<(int)(((long long)NN * 128 + 255) / 256), 256>>>(smaxu, smaxf, sum,
                                                                         (long long)NN * 128);
        expsum_kernel<<<(int)(((long long)TROWS * 32 + 255) / 256), 256>>>(msg, at, cl, on,
                                                                           smaxf, sum);
        updin_kernel<<<(int)(((long long)NN * 128 + 255) / 256), 256>>>(sum, smaxf, h, updin);

        // --- node update MLP + outer residual (in place on h) ---
        gemm_f32<0><<<gU2, 256, smem_bytes>>>(updin, wui, bui, nullptr, t, NN, 256, 256);
        gemm_f32<1><<<gU1, 256, smem_bytes>>>(t, wuo, buo, h, h, NN, 128, 256);
    }
}

// round 5
// speedup vs baseline: 1.3289x; 1.3289x over previous
#include <cuda_runtime.h>
#include <cuda_bf16.h>
#include <math.h>
#include <stdint.h>

#define NN      100000
#define A_AT    150000
#define TROWS   750000
#define SMOOTHF 12.0f
#define MPAD_A  150016   // 1172 * 128
#define MPAD_N  100096   // 782 * 128

// ---------------- scratch (static device globals; no allocations) ----------------
__device__ unsigned short g_xhi[(size_t)MPAD_A * 256];
__device__ unsigned short g_xlo[(size_t)MPAD_A * 256];
__device__ unsigned short g_hhi[(size_t)MPAD_A * 256];   // relation-MLP hidden (split)
__device__ unsigned short g_hlo[(size_t)MPAD_A * 256];
__device__ float          g_msg[(size_t)TROWS * 128];
__device__ unsigned       g_smaxu[(size_t)NN * 128];
__device__ float          g_smax[(size_t)NN * 128];
__device__ float          g_sum[(size_t)NN * 128];
__device__ unsigned short g_uhi[(size_t)MPAD_N * 256];   // updin (split)
__device__ unsigned short g_ulo[(size_t)MPAD_N * 256];
__device__ unsigned short g_thi[(size_t)MPAD_N * 256];   // update-MLP hidden (split)
__device__ unsigned short g_tlo[(size_t)MPAD_N * 256];
__device__ unsigned short g_whi[393216];                 // transposed [N,K] weights, hi
__device__ unsigned short g_wlo[393216];                 // lo

// ---------------- helpers ----------------
__device__ __forceinline__ void cp16(void* dst, const void* src) {
    unsigned d = (unsigned)__cvta_generic_to_shared(dst);
    asm volatile("cp.async.cg.shared.global [%0], [%1], 16;" :: "r"(d), "l"(src));
}
#define CP_COMMIT() asm volatile("cp.async.commit_group;")
#define CP_WAIT(n)  asm volatile("cp.async.wait_group %0;" :: "n"(n))

__device__ __forceinline__ void mma_bf16(float* c, const unsigned* a, unsigned b0, unsigned b1) {
    asm volatile("mma.sync.aligned.m16n8k16.row.col.f32.bf16.bf16.f32 "
                 "{%0,%1,%2,%3}, {%4,%5,%6,%7}, {%8,%9}, {%0,%1,%2,%3};"
                 : "+f"(c[0]), "+f"(c[1]), "+f"(c[2]), "+f"(c[3])
                 : "r"(a[0]), "r"(a[1]), "r"(a[2]), "r"(a[3]), "r"(b0), "r"(b1));
}
__device__ __forceinline__ unsigned cvt_bf16x2(float hi, float lo) {
    unsigned d; asm("cvt.rn.bf16x2.f32 %0, %1, %2;" : "=r"(d) : "f"(hi), "f"(lo)); return d;
}
__device__ __forceinline__ float bfbits(unsigned u16) { return __uint_as_float(u16 << 16); }

__device__ __forceinline__ float mish_f(float x) {
    float t = __expf(x);
    float u = fmaf(t, t, 2.f * t);
    float r = x * __fdividef(u, u + 2.f);
    return (x > 20.f) ? x : r;
}
// split v into truncated-hi bf16 + rn-lo bf16; returns packed pairs for (v0,v1)
__device__ __forceinline__ void split2(float v0, float v1, unsigned& hi, unsigned& lo) {
    unsigned u0 = __float_as_uint(v0), u1 = __float_as_uint(v1);
    hi = (u0 >> 16) | (u1 & 0xFFFF0000u);
    float l0 = v0 - __uint_as_float(u0 & 0xFFFF0000u);
    float l1 = v1 - __uint_as_float(u1 & 0xFFFF0000u);
    lo = cvt_bf16x2(l1, l0);
}
__device__ __forceinline__ unsigned encf(float f) {
    unsigned u = __float_as_uint(f);
    return (u & 0x80000000u) ? ~u : (u | 0x80000000u);
}
__device__ __forceinline__ float decf(unsigned u) {
    return (u & 0x80000000u) ? __uint_as_float(u & 0x7FFFFFFFu) : __uint_as_float(~u);
}

// ---------------- weight transpose/split: W[K,N] f32 -> [N,K] bf16 hi/lo ----------------
__global__ void convW(const float* __restrict__ W, unsigned short* __restrict__ hi,
                      unsigned short* __restrict__ lo, int K, int N)
{
    int i = blockIdx.x * blockDim.x + threadIdx.x;
    if (i >= K * N) return;
    int k = i / N, n = i - k * N;
    float x = W[i];
    unsigned u = __float_as_uint(x);
    float r = x - __uint_as_float(u & 0xFFFF0000u);
    __nv_bfloat16 lb = __float2bfloat16_rn(r);
    hi[(size_t)n * K + k] = (unsigned short)(u >> 16);
    lo[(size_t)n * K + k] = *(unsigned short*)&lb;
}

// ---------------- HMMA GEMM: C[M,N] = epi(A[M,K] @ W[K,N] + bias) ----------------
// A given as split bf16 pair [M,K]; W as transposed split [N,K].
// MODE 0: mish -> split bf16 out (Chi/Clo)
// MODE 1: f32 out = acc + bias + (Xhi+Xlo)
// MODE 2: f32 out = acc + bias + Xf
#define KC 32
#define STAGES 4
#define STAGE_BYTES 40960      // 4 tiles * 128 rows * 80B
#define OFF_AH 0
#define OFF_AL 10240
#define OFF_BH 20480
#define OFF_BL 30720

template<int MODE>
__global__ void __launch_bounds__(256, 1) gemm_hmma(
    const unsigned short* __restrict__ Ahi, const unsigned short* __restrict__ Alo,
    const unsigned short* __restrict__ Bhi, const unsigned short* __restrict__ Blo,
    const float* __restrict__ bias,
    const unsigned short* __restrict__ Xhi, const unsigned short* __restrict__ Xlo,
    const float* __restrict__ Xf,
    unsigned short* __restrict__ Chi, unsigned short* __restrict__ Clo,
    float* __restrict__ Cf,
    int M, int N, int K)
{
    extern __shared__ char sm[];
    const int tid  = threadIdx.x;
    const int wid  = tid >> 5, lane = tid & 31;
    const int g    = lane >> 2, t = lane & 3;
    const int wm   = wid & 3,  wn = wid >> 2;
    const int row0 = blockIdx.y * 128, col0 = blockIdx.x * 128;
    const int nc   = K >> 5;

    float c[2][8][4];
#pragma unroll
    for (int i = 0; i < 2; i++)
#pragma unroll
        for (int j = 0; j < 8; j++)
#pragma unroll
            for (int q = 0; q < 4; q++) c[i][j][q] = 0.f;

    auto issue = [&](int ch) {
        char* sb = sm + (ch & (STAGES - 1)) * STAGE_BYTES;
#pragma unroll
        for (int rep = 0; rep < 2; rep++) {
            int id  = tid + rep * 256;
            int row = id & 127, seg = id >> 7;
            size_t gA = (size_t)(row0 + row) * K + ch * KC + seg * 8;
            size_t gB = (size_t)(col0 + row) * K + ch * KC + seg * 8;
            int so = row * 80 + seg * 16;
            cp16(sb + OFF_AH + so, Ahi + gA);
            cp16(sb + OFF_AL + so, Alo + gA);
            cp16(sb + OFF_BH + so, Bhi + gB);
            cp16(sb + OFF_BL + so, Blo + gB);
        }
    };

    for (int s = 0; s < STAGES - 1 && s < nc; s++) { issue(s); CP_COMMIT(); }

    const int aB = (wm * 32 + g) * 80 + t * 4;
    const int bB = (wn * 64 + g) * 80 + t * 4;

#pragma unroll 1
    for (int ch = 0; ch < nc; ch++) {
        CP_WAIT(STAGES - 2);
        __syncthreads();
        char* sb = sm + (ch & (STAGES - 1)) * STAGE_BYTES;
#pragma unroll
        for (int ks = 0; ks < 2; ks++) {
            unsigned ah[2][4], al[2][4];
#pragma unroll
            for (int mt = 0; mt < 2; mt++) {
                int o = aB + mt * 1280 + ks * 32;
                ah[mt][0] = *(unsigned*)(sb + OFF_AH + o);
                ah[mt][1] = *(unsigned*)(sb + OFF_AH + o + 640);
                ah[mt][2] = *(unsigned*)(sb + OFF_AH + o + 16);
                ah[mt][3] = *(unsigned*)(sb + OFF_AH + o + 656);
                al[mt][0] = *(unsigned*)(sb + OFF_AL + o);
                al[mt][1] = *(unsigned*)(sb + OFF_AL + o + 640);
                al[mt][2] = *(unsigned*)(sb + OFF_AL + o + 16);
                al[mt][3] = *(unsigned*)(sb + OFF_AL + o + 656);
            }
#pragma unroll
            for (int nt = 0; nt < 8; nt++) {
                int o = bB + nt * 640 + ks * 32;
                unsigned bh0 = *(unsigned*)(sb + OFF_BH + o);
                unsigned bh1 = *(unsigned*)(sb + OFF_BH + o + 16);
                unsigned bl0 = *(unsigned*)(sb + OFF_BL + o);
                unsigned bl1 = *(unsigned*)(sb + OFF_BL + o + 16);
#pragma unroll
                for (int mt = 0; mt < 2; mt++) {
                    mma_bf16(c[mt][nt], ah[mt], bh0, bh1);   // hi*hi
                    mma_bf16(c[mt][nt], al[mt], bh0, bh1);   // lo*hi
                    mma_bf16(c[mt][nt], ah[mt], bl0, bl1);   // hi*lo
                }
            }
        }
        __syncthreads();
        int nxt = ch + STAGES - 1;
        if (nxt < nc) issue(nxt);
        CP_COMMIT();
    }

    // ---- epilogue ----
#pragma unroll
    for (int mt = 0; mt < 2; mt++)
#pragma unroll
    for (int half = 0; half < 2; half++) {
        int r = row0 + wm * 32 + mt * 16 + g + half * 8;
        if (r < M) {
#pragma unroll
            for (int nt = 0; nt < 8; nt++) {
                int col = col0 + wn * 64 + nt * 8 + t * 2;
                float v0 = c[mt][nt][half * 2 + 0] + __ldg(bias + col);
                float v1 = c[mt][nt][half * 2 + 1] + __ldg(bias + col + 1);
                size_t idx = (size_t)r * N + col;
                if (MODE == 0) {
                    v0 = mish_f(v0); v1 = mish_f(v1);
                    unsigned hi, lo;
                    split2(v0, v1, hi, lo);
                    *(unsigned*)(Chi + idx) = hi;
                    *(unsigned*)(Clo + idx) = lo;
                } else if (MODE == 1) {
                    unsigned xh = *(const unsigned*)(Xhi + idx);
                    unsigned xl = *(const unsigned*)(Xlo + idx);
                    v0 += bfbits(xh & 0xFFFFu) + bfbits(xl & 0xFFFFu);
                    v1 += bfbits(xh >> 16)     + bfbits(xl >> 16);
                    float2 o; o.x = v0; o.y = v1;
                    *(float2*)(Cf + idx) = o;
                } else {
                    float2 x = *(const float2*)(Xf + idx);
                    float2 o; o.x = v0 + x.x; o.y = v1 + x.y;
                    *(float2*)(Cf + idx) = o;
                }
            }
        }
    }
}

// ---------------- gather: x[seg] = split(h[av[seg]]) ----------------
__global__ void gather_split(const float* __restrict__ h, const int* __restrict__ av,
                             unsigned short* __restrict__ xhi, unsigned short* __restrict__ xlo,
                             long long nseg)
{
    long long i = (long long)blockIdx.x * blockDim.x + threadIdx.x;
    if (i >= nseg * 32) return;
    long long seg = i >> 5;
    int f4 = (int)(i & 31) * 4;
    int node = __ldg(av + seg);
    float4 v = *(const float4*)(h + (size_t)node * 128 + f4);
    unsigned h01, l01, h23, l23;
    split2(v.x, v.y, h01, l01);
    split2(v.z, v.w, h23, l23);
    *(uint2*)(xhi + seg * 128 + f4) = make_uint2(h01, h23);
    *(uint2*)(xlo + seg * 128 + f4) = make_uint2(l01, l23);
}

// ---------------- aggregation ----------------
__device__ __forceinline__ int row_to_node(long long row, const int* __restrict__ at,
                                           const int* __restrict__ cl, const int* __restrict__ on)
{
    if (row < 300000) return __ldg(at + row);
    if (row < 450000) return __ldg(cl + row - 300000);
    return __ldg(on + row - 450000);
}

__global__ void segmax_kernel(const float* __restrict__ msg,
                              const int* __restrict__ at, const int* __restrict__ cl,
                              const int* __restrict__ on, unsigned* __restrict__ smax)
{
    long long i = (long long)blockIdx.x * blockDim.x + threadIdx.x;
    if (i >= (long long)TROWS * 32) return;
    long long row = i >> 5;
    int f4 = (int)(i & 31) * 4;
    int node = row_to_node(row, at, cl, on);
    float4 v = *(const float4*)(msg + row * 128 + f4);
    unsigned* p = smax + (size_t)node * 128 + f4;
    atomicMax(p + 0, encf(v.x));
    atomicMax(p + 1, encf(v.y));
    atomicMax(p + 2, encf(v.z));
    atomicMax(p + 3, encf(v.w));
}

__global__ void decode_kernel(const unsigned* __restrict__ smaxu, float* __restrict__ smax,
                              float* __restrict__ sum, long long n)
{
    long long i = (long long)blockIdx.x * blockDim.x + threadIdx.x;
    if (i >= n) return;
    unsigned u = smaxu[i];
    smax[i] = (u == 0u) ? 0.f : decf(u);
    sum[i]  = 0.f;
}

__global__ void expsum_kernel(const float* __restrict__ msg,
                              const int* __restrict__ at, const int* __restrict__ cl,
                              const int* __restrict__ on, const float* __restrict__ smax,
                              float* __restrict__ sum)
{
    long long i = (long long)blockIdx.x * blockDim.x + threadIdx.x;
    if (i >= (long long)TROWS * 32) return;
    long long row = i >> 5;
    int f4 = (int)(i & 31) * 4;
    int node = row_to_node(row, at, cl, on);
    float4 v = *(const float4*)(msg + row * 128 + f4);
    const float4 m = *(const float4*)(smax + (size_t)node * 128 + f4);
    float* p = sum + (size_t)node * 128 + f4;
    atomicAdd(p + 0, __expf(SMOOTHF * (v.x - m.x)));
    atomicAdd(p + 1, __expf(SMOOTHF * (v.y - m.y)));
    atomicAdd(p + 2, __expf(SMOOTHF * (v.z - m.z)));
    atomicAdd(p + 3, __expf(SMOOTHF * (v.w - m.w)));
}

__global__ void updin_kernel(const float* __restrict__ sum, const float* __restrict__ smax,
                             const float* __restrict__ h,
                             unsigned short* __restrict__ uhi, unsigned short* __restrict__ ulo)
{
    long long i = (long long)blockIdx.x * blockDim.x + threadIdx.x;
    if (i >= (long long)NN * 64) return;     // 2 elems per thread
    long long node = i >> 6;
    int e = (int)(i & 63) * 2;
    size_t bi = node * 128 + e;
    float m0 = logf(sum[bi] + 1e-16f) / SMOOTHF + smax[bi];
    float m1 = logf(sum[bi + 1] + 1e-16f) / SMOOTHF + smax[bi + 1];
    unsigned hh, ll;
    split2(m0, m1, hh, ll);
    *(unsigned*)(uhi + node * 256 + e) = hh;
    *(unsigned*)(ulo + node * 256 + e) = ll;
    float h0 = h[bi], h1 = h[bi + 1];
    split2(h0, h1, hh, ll);
    *(unsigned*)(uhi + node * 256 + 128 + e) = hh;
    *(unsigned*)(ulo + node * 256 + 128 + e) = ll;
}

// ---------------- host launch ----------------
extern "C" void kernel_launch(void* const* d_in, const int* in_sizes, int n_in,
                              void* d_out, int out_size)
{
    const float *emb, *w_in[3], *b_in[3], *w_out[3], *b_out[3], *wui, *bui, *wuo, *buo;
    const int *at, *cl, *on;

    if (in_sizes[2] == 65536) {
        emb = (const float*)d_in[0];
        at  = (const int*)d_in[1];
        w_in[0] = (const float*)d_in[2];  b_in[0] = (const float*)d_in[3];
        w_out[0] = (const float*)d_in[4]; b_out[0] = (const float*)d_in[5];
        cl  = (const int*)d_in[6];
        w_in[1] = (const float*)d_in[7];  b_in[1] = (const float*)d_in[8];
        w_out[1] = (const float*)d_in[9]; b_out[1] = (const float*)d_in[10];
        on  = (const int*)d_in[11];
        w_in[2] = (const float*)d_in[12];  b_in[2] = (const float*)d_in[13];
        w_out[2] = (const float*)d_in[14]; b_out[2] = (const float*)d_in[15];
        wui = (const float*)d_in[16]; bui = (const float*)d_in[17];
        wuo = (const float*)d_in[18]; buo = (const float*)d_in[19];
    } else {
        emb = (const float*)d_in[0];
        at  = (const int*)d_in[1];
        cl  = (const int*)d_in[2];
        on  = (const int*)d_in[3];
        w_in[0] = (const float*)d_in[4];  b_in[0] = (const float*)d_in[5];
        w_out[0] = (const float*)d_in[6]; b_out[0] = (const float*)d_in[7];
        w_in[1] = (const float*)d_in[8];  b_in[1] = (const float*)d_in[9];
        w_out[1] = (const float*)d_in[10]; b_out[1] = (const float*)d_in[11];
        w_in[2] = (const float*)d_in[12];  b_in[2] = (const float*)d_in[13];
        w_out[2] = (const float*)d_in[14]; b_out[2] = (const float*)d_in[15];
        wui = (const float*)d_in[16]; bui = (const float*)d_in[17];
        wuo = (const float*)d_in[18]; buo = (const float*)d_in[19];
    }

    float* h = (float*)d_out;
    unsigned short *xhi, *xlo, *hhi, *hlo, *uhi, *ulo, *thi, *tlo, *whi, *wlo;
    float *msg, *smaxf, *sum;
    unsigned* smaxu;
    cudaGetSymbolAddress((void**)&xhi, g_xhi);  cudaGetSymbolAddress((void**)&xlo, g_xlo);
    cudaGetSymbolAddress((void**)&hhi, g_hhi);  cudaGetSymbolAddress((void**)&hlo, g_hlo);
    cudaGetSymbolAddress((void**)&uhi, g_uhi);  cudaGetSymbolAddress((void**)&ulo, g_ulo);
    cudaGetSymbolAddress((void**)&thi, g_thi);  cudaGetSymbolAddress((void**)&tlo, g_tlo);
    cudaGetSymbolAddress((void**)&whi, g_whi);  cudaGetSymbolAddress((void**)&wlo, g_wlo);
    cudaGetSymbolAddress((void**)&msg, g_msg);
    cudaGetSymbolAddress((void**)&smaxu, g_smaxu);
    cudaGetSymbolAddress((void**)&smaxf, g_smax);
    cudaGetSymbolAddress((void**)&sum, g_sum);

    // transposed-split weight offsets (ushort units)
    const size_t O_AT_IN = 0, O_AT_OUT = 65536, O_CL_IN = 131072, O_CL_OUT = 147456,
                 O_ON_IN = 163840, O_ON_OUT = 229376, O_U_IN = 294912, O_U_OUT = 360448;

    struct { const float* w; size_t off; int K, N; } cw[8] = {
        { w_in[0],  O_AT_IN,  256, 256 }, { w_out[0], O_AT_OUT, 256, 256 },
        { w_in[1],  O_CL_IN,  128, 128 }, { w_out[1], O_CL_OUT, 128, 128 },
        { w_in[2],  O_ON_IN,  256, 256 }, { w_out[2], O_ON_OUT, 256, 256 },
        { wui,      O_U_IN,   256, 256 }, { wuo,      O_U_OUT,  256, 128 },
    };
    for (int i = 0; i < 8; i++) {
        int tot = cw[i].K * cw[i].N;
        convW<<<(tot + 255) / 256, 256>>>(cw[i].w, whi + cw[i].off, wlo + cw[i].off,
                                          cw[i].K, cw[i].N);
    }

    const int SMEM = STAGES * STAGE_BYTES;   // 163840
    cudaFuncSetAttribute(gemm_hmma<0>, cudaFuncAttributeMaxDynamicSharedMemorySize, SMEM);
    cudaFuncSetAttribute(gemm_hmma<1>, cudaFuncAttributeMaxDynamicSharedMemorySize, SMEM);
    cudaFuncSetAttribute(gemm_hmma<2>, cudaFuncAttributeMaxDynamicSharedMemorySize, SMEM);

    cudaMemcpyAsync(h, emb, (size_t)NN * 128 * sizeof(float), cudaMemcpyDeviceToDevice);

    const dim3 gA2(2, MPAD_A / 128), gA1(1, MPAD_A / 128);
    const dim3 gN2(2, MPAD_N / 128), gN1(1, MPAD_N / 128);

    for (int layer = 0; layer < 4; layer++) {
        // --- at (ar=2, d=256) -> msg rows [0, 300000) ---
        gather_split<<<(int)((300000LL * 32 + 255) / 256), 256>>>(h, at, xhi, xlo, 300000);
        gemm_hmma<0><<<gA2, 256, SMEM>>>(xhi, xlo, whi + O_AT_IN, wlo + O_AT_IN, b_in[0],
                                         nullptr, nullptr, nullptr, hhi, hlo, nullptr,
                                         A_AT, 256, 256);
        gemm_hmma<1><<<gA2, 256, SMEM>>>(hhi, hlo, whi + O_AT_OUT, wlo + O_AT_OUT, b_out[0],
                                         xhi, xlo, nullptr, nullptr, nullptr, msg,
                                         A_AT, 256, 256);

        // --- clear (ar=1, d=128) -> msg rows [300000, 450000) ---
        gather_split<<<(int)((150000LL * 32 + 255) / 256), 256>>>(h, cl, xhi, xlo, 150000);
        gemm_hmma<0><<<gA1, 256, SMEM>>>(xhi, xlo, whi + O_CL_IN, wlo + O_CL_IN, b_in[1],
                                         nullptr, nullptr, nullptr, hhi, hlo, nullptr,
                                         A_AT, 128, 128);
        gemm_hmma<1><<<gA1, 256, SMEM>>>(hhi, hlo, whi + O_CL_OUT, wlo + O_CL_OUT, b_out[1],
                                         xhi, xlo, nullptr, nullptr, nullptr,
                                         msg + (size_t)300000 * 128, A_AT, 128, 128);

        // --- on (ar=2, d=256) -> msg rows [450000, 750000) ---
        gather_split<<<(int)((300000LL * 32 + 255) / 256), 256>>>(h, on, xhi, xlo, 300000);
        gemm_hmma<0><<<gA2, 256, SMEM>>>(xhi, xlo, whi + O_ON_IN, wlo + O_ON_IN, b_in[2],
                                         nullptr, nullptr, nullptr, hhi, hlo, nullptr,
                                         A_AT, 256, 256);
        gemm_hmma<1><<<gA2, 256, SMEM>>>(hhi, hlo, whi + O_ON_OUT, wlo + O_ON_OUT, b_out[2],
                                         xhi, xlo, nullptr, nullptr, nullptr,
                                         msg + (size_t)450000 * 128, A_AT, 256, 256);

        // --- smooth-max aggregation ---
        cudaMemsetAsync(smaxu, 0, (size_t)NN * 128 * sizeof(unsigned));
        segmax_kernel<<<(int)(((long long)TROWS * 32 + 255) / 256), 256>>>(msg, at, cl, on, smaxu);
        decode_kernel<<<(int)(((long long)NN * 128 + 255) / 256), 256>>>(smaxu, smaxf, sum,
                                                                         (long long)NN * 128);
        expsum_kernel<<<(int)(((long long)TROWS * 32 + 255) / 256), 256>>>(msg, at, cl, on,
                                                                           smaxf, sum);
        updin_kernel<<<(int)(((long long)NN * 64 + 255) / 256), 256>>>(sum, smaxf, h, uhi, ulo);

        // --- node update MLP + outer residual (h in place) ---
        gemm_hmma<0><<<gN2, 256, SMEM>>>(uhi, ulo, whi + O_U_IN, wlo + O_U_IN, bui,
                                         nullptr, nullptr, nullptr, thi, tlo, nullptr,
                                         NN, 256, 256);
        gemm_hmma<2><<<gN1, 256, SMEM>>>(thi, tlo, whi + O_U_OUT, wlo + O_U_OUT, buo,
                                         nullptr, nullptr, h, nullptr, nullptr, h,
                                         NN, 128, 256);
    }
}

// round 6
// speedup vs baseline: 1.4909x; 1.1219x over previous
#include <cuda_runtime.h>
#include <cuda_bf16.h>
#include <math.h>
#include <stdint.h>

#define NN      100000
#define A_AT    150000
#define TROWS   750000
#define SMOOTHF 12.0f
#define MPAD_A  150016   // 1172 * 128
#define MPAD_N  100096   // 782 * 128

// ---------------- scratch (static device globals; no allocations) ----------------
__device__ unsigned short g_xhi[(size_t)MPAD_A * 256];
__device__ unsigned short g_xlo[(size_t)MPAD_A * 256];
__device__ unsigned short g_hhi[(size_t)MPAD_A * 256];
__device__ unsigned short g_hlo[(size_t)MPAD_A * 256];
__device__ float          g_msg[(size_t)TROWS * 128];
__device__ unsigned       g_smaxu[(size_t)NN * 128];
__device__ float          g_smax[(size_t)NN * 128];
__device__ float          g_sum[(size_t)NN * 128];
__device__ unsigned short g_uhi[(size_t)MPAD_N * 256];
__device__ unsigned short g_ulo[(size_t)MPAD_N * 256];
__device__ unsigned short g_thi[(size_t)MPAD_N * 256];
__device__ unsigned short g_tlo[(size_t)MPAD_N * 256];
__device__ unsigned short g_whi[393216];
__device__ unsigned short g_wlo[393216];

// ---------------- helpers ----------------
__device__ __forceinline__ void cp16(void* dst, const void* src) {
    unsigned d = (unsigned)__cvta_generic_to_shared(dst);
    asm volatile("cp.async.cg.shared.global [%0], [%1], 16;" :: "r"(d), "l"(src));
}
#define CP_COMMIT() asm volatile("cp.async.commit_group;")
#define CP_WAIT(n)  asm volatile("cp.async.wait_group %0;" :: "n"(n))

__device__ __forceinline__ void mma_bf16(float* c, const unsigned* a, unsigned b0, unsigned b1) {
    asm volatile("mma.sync.aligned.m16n8k16.row.col.f32.bf16.bf16.f32 "
                 "{%0,%1,%2,%3}, {%4,%5,%6,%7}, {%8,%9}, {%0,%1,%2,%3};"
                 : "+f"(c[0]), "+f"(c[1]), "+f"(c[2]), "+f"(c[3])
                 : "r"(a[0]), "r"(a[1]), "r"(a[2]), "r"(a[3]), "r"(b0), "r"(b1));
}
__device__ __forceinline__ unsigned cvt_bf16x2(float hi, float lo) {
    unsigned d; asm("cvt.rn.bf16x2.f32 %0, %1, %2;" : "=r"(d) : "f"(hi), "f"(lo)); return d;
}
__device__ __forceinline__ float bfbits(unsigned u16) { return __uint_as_float(u16 << 16); }

__device__ __forceinline__ float mish_f(float x) {
    float t = __expf(x);
    float u = fmaf(t, t, 2.f * t);
    float r = x * __fdividef(u, u + 2.f);
    return (x > 20.f) ? x : r;
}
__device__ __forceinline__ void split2(float v0, float v1, unsigned& hi, unsigned& lo) {
    unsigned u0 = __float_as_uint(v0), u1 = __float_as_uint(v1);
    hi = (u0 >> 16) | (u1 & 0xFFFF0000u);
    float l0 = v0 - __uint_as_float(u0 & 0xFFFF0000u);
    float l1 = v1 - __uint_as_float(u1 & 0xFFFF0000u);
    lo = cvt_bf16x2(l1, l0);
}
__device__ __forceinline__ unsigned encf(float f) {
    unsigned u = __float_as_uint(f);
    return (u & 0x80000000u) ? ~u : (u | 0x80000000u);
}
__device__ __forceinline__ float decf(unsigned u) {
    return (u & 0x80000000u) ? __uint_as_float(u & 0x7FFFFFFFu) : __uint_as_float(~u);
}

// ---------------- fused weight transpose/split (ONE launch): W[K,N] f32 -> [N,K] bf16 hi/lo ----------------
// segment boundaries == destination offsets in g_whi/g_wlo
__global__ void convW_all(const float* __restrict__ w0, const float* __restrict__ w1,
                          const float* __restrict__ w2, const float* __restrict__ w3,
                          const float* __restrict__ w4, const float* __restrict__ w5,
                          const float* __restrict__ w6, const float* __restrict__ w7,
                          unsigned short* __restrict__ hi, unsigned short* __restrict__ lo)
{
    int i = blockIdx.x * blockDim.x + threadIdx.x;
    if (i >= 393216) return;
    const float* W; int base, K, N;
    if      (i < 131072) { if (i < 65536)  { W = w0; base = 0;      } else { W = w1; base = 65536;  } K = 256; N = 256; }
    else if (i < 163840) { if (i < 147456) { W = w2; base = 131072; } else { W = w3; base = 147456; } K = 128; N = 128; }
    else if (i < 294912) { if (i < 229376) { W = w4; base = 163840; } else { W = w5; base = 229376; } K = 256; N = 256; }
    else if (i < 360448) { W = w6; base = 294912; K = 256; N = 256; }
    else                 { W = w7; base = 360448; K = 256; N = 128; }
    int li = i - base;
    int k = li / N, n = li - k * N;
    float x = W[li];
    unsigned u = __float_as_uint(x);
    float r = x - __uint_as_float(u & 0xFFFF0000u);
    __nv_bfloat16 lb = __float2bfloat16_rn(r);
    hi[(size_t)base + (size_t)n * K + k] = (unsigned short)(u >> 16);
    lo[(size_t)base + (size_t)n * K + k] = *(unsigned short*)&lb;
}

// ---------------- HMMA GEMM: C[M,N] = epi(A[M,K] @ W[K,N] + bias) ----------------
// MODE 0: mish -> split bf16 out; MODE 1: f32 out = acc+bias+(Xhi+Xlo); MODE 2: f32 out = acc+bias+Xf
#define KC 32
#define STAGE_BYTES 40960
#define OFF_AH 0
#define OFF_AL 10240
#define OFF_BH 20480
#define OFF_BL 30720

template<int MODE>
__global__ void __launch_bounds__(256, 2) gemm_hmma(
    const unsigned short* __restrict__ Ahi, const unsigned short* __restrict__ Alo,
    const unsigned short* __restrict__ Bhi, const unsigned short* __restrict__ Blo,
    const float* __restrict__ bias,
    const unsigned short* __restrict__ Xhi, const unsigned short* __restrict__ Xlo,
    const float* __restrict__ Xf,
    unsigned short* __restrict__ Chi, unsigned short* __restrict__ Clo,
    float* __restrict__ Cf,
    int M, int N, int K)
{
    extern __shared__ char sm[];
    const int tid  = threadIdx.x;
    const int wid  = tid >> 5, lane = tid & 31;
    const int g    = lane >> 2, t = lane & 3;
    const int wm   = wid & 3,  wn = wid >> 2;
    const int row0 = blockIdx.y * 128, col0 = blockIdx.x * 128;
    const int nc   = K >> 5;

    float c[2][8][4];
#pragma unroll
    for (int i = 0; i < 2; i++)
#pragma unroll
        for (int j = 0; j < 8; j++)
#pragma unroll
            for (int q = 0; q < 4; q++) c[i][j][q] = 0.f;

    auto issue = [&](int ch) {
        char* sb = sm + (ch & 1) * STAGE_BYTES;
#pragma unroll
        for (int rep = 0; rep < 2; rep++) {
            int id  = tid + rep * 256;
            int row = id & 127, seg = id >> 7;
            size_t gA = (size_t)(row0 + row) * K + ch * KC + seg * 8;
            size_t gB = (size_t)(col0 + row) * K + ch * KC + seg * 8;
            int so = row * 80 + seg * 16;
            cp16(sb + OFF_AH + so, Ahi + gA);
            cp16(sb + OFF_AL + so, Alo + gA);
            cp16(sb + OFF_BH + so, Bhi + gB);
            cp16(sb + OFF_BL + so, Blo + gB);
        }
    };

    issue(0); CP_COMMIT();

    const int aB = (wm * 32 + g) * 80 + t * 4;
    const int bB = (wn * 64 + g) * 80 + t * 4;

#pragma unroll 1
    for (int ch = 0; ch < nc; ch++) {
        if (ch + 1 < nc) { issue(ch + 1); CP_COMMIT(); CP_WAIT(1); }
        else             { CP_WAIT(0); }
        __syncthreads();
        char* sb = sm + (ch & 1) * STAGE_BYTES;
#pragma unroll
        for (int ks = 0; ks < 2; ks++) {
            unsigned ah[2][4], al[2][4];
#pragma unroll
            for (int mt = 0; mt < 2; mt++) {
                int o = aB + mt * 1280 + ks * 32;
                ah[mt][0] = *(unsigned*)(sb + OFF_AH + o);
                ah[mt][1] = *(unsigned*)(sb + OFF_AH + o + 640);
                ah[mt][2] = *(unsigned*)(sb + OFF_AH + o + 16);
                ah[mt][3] = *(unsigned*)(sb + OFF_AH + o + 656);
                al[mt][0] = *(unsigned*)(sb + OFF_AL + o);
                al[mt][1] = *(unsigned*)(sb + OFF_AL + o + 640);
                al[mt][2] = *(unsigned*)(sb + OFF_AL + o + 16);
                al[mt][3] = *(unsigned*)(sb + OFF_AL + o + 656);
            }
#pragma unroll
            for (int nt = 0; nt < 8; nt++) {
                int o = bB + nt * 640 + ks * 32;
                unsigned bh0 = *(unsigned*)(sb + OFF_BH + o);
                unsigned bh1 = *(unsigned*)(sb + OFF_BH + o + 16);
                unsigned bl0 = *(unsigned*)(sb + OFF_BL + o);
                unsigned bl1 = *(unsigned*)(sb + OFF_BL + o + 16);
#pragma unroll
                for (int mt = 0; mt < 2; mt++) {
                    mma_bf16(c[mt][nt], ah[mt], bh0, bh1);
                    mma_bf16(c[mt][nt], al[mt], bh0, bh1);
                    mma_bf16(c[mt][nt], ah[mt], bl0, bl1);
                }
            }
        }
        __syncthreads();
    }

    // ---- epilogue ----
#pragma unroll
    for (int mt = 0; mt < 2; mt++)
#pragma unroll
    for (int half = 0; half < 2; half++) {
        int r = row0 + wm * 32 + mt * 16 + g + half * 8;
        if (r < M) {
#pragma unroll
            for (int nt = 0; nt < 8; nt++) {
                int col = col0 + wn * 64 + nt * 8 + t * 2;
                float v0 = c[mt][nt][half * 2 + 0] + __ldg(bias + col);
                float v1 = c[mt][nt][half * 2 + 1] + __ldg(bias + col + 1);
                size_t idx = (size_t)r * N + col;
                if (MODE == 0) {
                    v0 = mish_f(v0); v1 = mish_f(v1);
                    unsigned hi, lo;
                    split2(v0, v1, hi, lo);
                    *(unsigned*)(Chi + idx) = hi;
                    *(unsigned*)(Clo + idx) = lo;
                } else if (MODE == 1) {
                    unsigned xh = *(const unsigned*)(Xhi + idx);
                    unsigned xl = *(const unsigned*)(Xlo + idx);
                    v0 += bfbits(xh & 0xFFFFu) + bfbits(xl & 0xFFFFu);
                    v1 += bfbits(xh >> 16)     + bfbits(xl >> 16);
                    float2 o; o.x = v0; o.y = v1;
                    *(float2*)(Cf + idx) = o;
                } else {
                    float2 x = *(const float2*)(Xf + idx);
                    float2 o; o.x = v0 + x.x; o.y = v1 + x.y;
                    *(float2*)(Cf + idx) = o;
                }
            }
        }
    }
}

// ---------------- gather: x[seg] = split(h[av[seg]]) ----------------
__global__ void gather_split(const float* __restrict__ h, const int* __restrict__ av,
                             unsigned short* __restrict__ xhi, unsigned short* __restrict__ xlo,
                             long long nseg)
{
    long long i = (long long)blockIdx.x * blockDim.x + threadIdx.x;
    if (i >= nseg * 32) return;
    long long seg = i >> 5;
    int f4 = (int)(i & 31) * 4;
    int node = __ldg(av + seg);
    float4 v = *(const float4*)(h + (size_t)node * 128 + f4);
    unsigned h01, l01, h23, l23;
    split2(v.x, v.y, h01, l01);
    split2(v.z, v.w, h23, l23);
    *(uint2*)(xhi + seg * 128 + f4) = make_uint2(h01, h23);
    *(uint2*)(xlo + seg * 128 + f4) = make_uint2(l01, l23);
}

// ---------------- aggregation ----------------
__device__ __forceinline__ int row_to_node(long long row, const int* __restrict__ at,
                                           const int* __restrict__ cl, const int* __restrict__ on)
{
    if (row < 300000) return __ldg(at + row);
    if (row < 450000) return __ldg(cl + row - 300000);
    return __ldg(on + row - 450000);
}

__global__ void segmax_kernel(const float* __restrict__ msg,
                              const int* __restrict__ at, const int* __restrict__ cl,
                              const int* __restrict__ on, unsigned* __restrict__ smax)
{
    long long i = (long long)blockIdx.x * blockDim.x + threadIdx.x;
    if (i >= (long long)TROWS * 32) return;
    long long row = i >> 5;
    int f4 = (int)(i & 31) * 4;
    int node = row_to_node(row, at, cl, on);
    float4 v = *(const float4*)(msg + row * 128 + f4);
    unsigned* p = smax + (size_t)node * 128 + f4;
    atomicMax(p + 0, encf(v.x));
    atomicMax(p + 1, encf(v.y));
    atomicMax(p + 2, encf(v.z));
    atomicMax(p + 3, encf(v.w));
}

__global__ void decode_kernel(const unsigned* __restrict__ smaxu, float* __restrict__ smax,
                              float* __restrict__ sum, long long n)
{
    long long i = (long long)blockIdx.x * blockDim.x + threadIdx.x;
    if (i >= n) return;
    unsigned u = smaxu[i];
    smax[i] = (u == 0u) ? 0.f : decf(u);
    sum[i]  = 0.f;
}

__global__ void expsum_kernel(const float* __restrict__ msg,
                              const int* __restrict__ at, const int* __restrict__ cl,
                              const int* __restrict__ on, const float* __restrict__ smax,
                              float* __restrict__ sum)
{
    long long i = (long long)blockIdx.x * blockDim.x + threadIdx.x;
    if (i >= (long long)TROWS * 32) return;
    long long row = i >> 5;
    int f4 = (int)(i & 31) * 4;
    int node = row_to_node(row, at, cl, on);
    float4 v = *(const float4*)(msg + row * 128 + f4);
    const float4 m = *(const float4*)(smax + (size_t)node * 128 + f4);
    float* p = sum + (size_t)node * 128 + f4;
    atomicAdd(p + 0, __expf(SMOOTHF * (v.x - m.x)));
    atomicAdd(p + 1, __expf(SMOOTHF * (v.y - m.y)));
    atomicAdd(p + 2, __expf(SMOOTHF * (v.z - m.z)));
    atomicAdd(p + 3, __expf(SMOOTHF * (v.w - m.w)));
}

__global__ void updin_kernel(const float* __restrict__ sum, const float* __restrict__ smax,
                             const float* __restrict__ h,
                             unsigned short* __restrict__ uhi, unsigned short* __restrict__ ulo)
{
    long long i = (long long)blockIdx.x * blockDim.x + threadIdx.x;
    if (i >= (long long)NN * 64) return;
    long long node = i >> 6;
    int e = (int)(i & 63) * 2;
    size_t bi = node * 128 + e;
    float m0 = logf(sum[bi] + 1e-16f) / SMOOTHF + smax[bi];
    float m1 = logf(sum[bi + 1] + 1e-16f) / SMOOTHF + smax[bi + 1];
    unsigned hh, ll;
    split2(m0, m1, hh, ll);
    *(unsigned*)(uhi + node * 256 + e) = hh;
    *(unsigned*)(ulo + node * 256 + e) = ll;
    float h0 = h[bi], h1 = h[bi + 1];
    split2(h0, h1, hh, ll);
    *(unsigned*)(uhi + node * 256 + 128 + e) = hh;
    *(unsigned*)(ulo + node * 256 + 128 + e) = ll;
}

// ---------------- host launch ----------------
extern "C" void kernel_launch(void* const* d_in, const int* in_sizes, int n_in,
                              void* d_out, int out_size)
{
    const float *emb, *w_in[3], *b_in[3], *w_out[3], *b_out[3], *wui, *bui, *wuo, *buo;
    const int *at, *cl, *on;

    if (in_sizes[2] == 65536) {
        emb = (const float*)d_in[0];
        at  = (const int*)d_in[1];
        w_in[0] = (const float*)d_in[2];  b_in[0] = (const float*)d_in[3];
        w_out[0] = (const float*)d_in[4]; b_out[0] = (const float*)d_in[5];
        cl  = (const int*)d_in[6];
        w_in[1] = (const float*)d_in[7];  b_in[1] = (const float*)d_in[8];
        w_out[1] = (const float*)d_in[9]; b_out[1] = (const float*)d_in[10];
        on  = (const int*)d_in[11];
        w_in[2] = (const float*)d_in[12];  b_in[2] = (const float*)d_in[13];
        w_out[2] = (const float*)d_in[14]; b_out[2] = (const float*)d_in[15];
        wui = (const float*)d_in[16]; bui = (const float*)d_in[17];
        wuo = (const float*)d_in[18]; buo = (const float*)d_in[19];
    } else {
        emb = (const float*)d_in[0];
        at  = (const int*)d_in[1];
        cl  = (const int*)d_in[2];
        on  = (const int*)d_in[3];
        w_in[0] = (const float*)d_in[4];  b_in[0] = (const float*)d_in[5];
        w_out[0] = (const float*)d_in[6]; b_out[0] = (const float*)d_in[7];
        w_in[1] = (const float*)d_in[8];  b_in[1] = (const float*)d_in[9];
        w_out[1] = (const float*)d_in[10]; b_out[1] = (const float*)d_in[11];
        w_in[2] = (const float*)d_in[12];  b_in[2] = (const float*)d_in[13];
        w_out[2] = (const float*)d_in[14]; b_out[2] = (const float*)d_in[15];
        wui = (const float*)d_in[16]; bui = (const float*)d_in[17];
        wuo = (const float*)d_in[18]; buo = (const float*)d_in[19];
    }

    float* h = (float*)d_out;
    unsigned short *xhi, *xlo, *hhi, *hlo, *uhi, *ulo, *thi, *tlo, *whi, *wlo;
    float *msg, *smaxf, *sum;
    unsigned* smaxu;
    cudaGetSymbolAddress((void**)&xhi, g_xhi);  cudaGetSymbolAddress((void**)&xlo, g_xlo);
    cudaGetSymbolAddress((void**)&hhi, g_hhi);  cudaGetSymbolAddress((void**)&hlo, g_hlo);
    cudaGetSymbolAddress((void**)&uhi, g_uhi);  cudaGetSymbolAddress((void**)&ulo, g_ulo);
    cudaGetSymbolAddress((void**)&thi, g_thi);  cudaGetSymbolAddress((void**)&tlo, g_tlo);
    cudaGetSymbolAddress((void**)&whi, g_whi);  cudaGetSymbolAddress((void**)&wlo, g_wlo);
    cudaGetSymbolAddress((void**)&msg, g_msg);
    cudaGetSymbolAddress((void**)&smaxu, g_smaxu);
    cudaGetSymbolAddress((void**)&smaxf, g_smax);
    cudaGetSymbolAddress((void**)&sum, g_sum);

    // transposed-split weight offsets (ushort units) — match convW_all segment bases
    const size_t O_AT_IN = 0, O_AT_OUT = 65536, O_CL_IN = 131072, O_CL_OUT = 147456,
                 O_ON_IN = 163840, O_ON_OUT = 229376, O_U_IN = 294912, O_U_OUT = 360448;

    convW_all<<<(393216 + 255) / 256, 256>>>(w_in[0], w_out[0], w_in[1], w_out[1],
                                             w_in[2], w_out[2], wui, wuo, whi, wlo);

    const int SMEM = 2 * STAGE_BYTES;   // 81920
    cudaFuncSetAttribute(gemm_hmma<0>, cudaFuncAttributeMaxDynamicSharedMemorySize, SMEM);
    cudaFuncSetAttribute(gemm_hmma<1>, cudaFuncAttributeMaxDynamicSharedMemorySize, SMEM);
    cudaFuncSetAttribute(gemm_hmma<2>, cudaFuncAttributeMaxDynamicSharedMemorySize, SMEM);

    cudaMemcpyAsync(h, emb, (size_t)NN * 128 * sizeof(float), cudaMemcpyDeviceToDevice);

    const dim3 gA2(2, MPAD_A / 128), gA1(1, MPAD_A / 128);
    const dim3 gN2(2, MPAD_N / 128), gN1(1, MPAD_N / 128);

    for (int layer = 0; layer < 4; layer++) {
        // --- at (ar=2, d=256) -> msg rows [0, 300000) ---
        gather_split<<<(int)((300000LL * 32 + 255) / 256), 256>>>(h, at, xhi, xlo, 300000);
        gemm_hmma<0><<<gA2, 256, SMEM>>>(xhi, xlo, whi + O_AT_IN, wlo + O_AT_IN, b_in[0],
                                         nullptr, nullptr, nullptr, hhi, hlo, nullptr,
                                         A_AT, 256, 256);
        gemm_hmma<1><<<gA2, 256, SMEM>>>(hhi, hlo, whi + O_AT_OUT, wlo + O_AT_OUT, b_out[0],
                                         xhi, xlo, nullptr, nullptr, nullptr, msg,
                                         A_AT, 256, 256);

        // --- clear (ar=1, d=128) -> msg rows [300000, 450000) ---
        gather_split<<<(int)((150000LL * 32 + 255) / 256), 256>>>(h, cl, xhi, xlo, 150000);
        gemm_hmma<0><<<gA1, 256, SMEM>>>(xhi, xlo, whi + O_CL_IN, wlo + O_CL_IN, b_in[1],
                                         nullptr, nullptr, nullptr, hhi, hlo, nullptr,
                                         A_AT, 128, 128);
        gemm_hmma<1><<<gA1, 256, SMEM>>>(hhi, hlo, whi + O_CL_OUT, wlo + O_CL_OUT, b_out[1],
                                         xhi, xlo, nullptr, nullptr, nullptr,
                                         msg + (size_t)300000 * 128, A_AT, 128, 128);

        // --- on (ar=2, d=256) -> msg rows [450000, 750000) ---
        gather_split<<<(int)((300000LL * 32 + 255) / 256), 256>>>(h, on, xhi, xlo, 300000);
        gemm_hmma<0><<<gA2, 256, SMEM>>>(xhi, xlo, whi + O_ON_IN, wlo + O_ON_IN, b_in[2],
                                         nullptr, nullptr, nullptr, hhi, hlo, nullptr,
                                         A_AT, 256, 256);
        gemm_hmma<1><<<gA2, 256, SMEM>>>(hhi, hlo, whi + O_ON_OUT, wlo + O_ON_OUT, b_out[2],
                                         xhi, xlo, nullptr, nullptr, nullptr,
                                         msg + (size_t)450000 * 128, A_AT, 256, 256);

        // --- smooth-max aggregation ---
        cudaMemsetAsync(smaxu, 0, (size_t)NN * 128 * sizeof(unsigned));
        segmax_kernel<<<(int)(((long long)TROWS * 32 + 255) / 256), 256>>>(msg, at, cl, on, smaxu);
        decode_kernel<<<(int)(((long long)NN * 128 + 255) / 256), 256>>>(smaxu, smaxf, sum,
                                                                         (long long)NN * 128);
        expsum_kernel<<<(int)(((long long)TROWS * 32 + 255) / 256), 256>>>(msg, at, cl, on,
                                                                           smaxf, sum);
        updin_kernel<<<(int)(((long long)NN * 64 + 255) / 256), 256>>>(sum, smaxf, h, uhi, ulo);

        // --- node update MLP + outer residual (h in place) ---
        gemm_hmma<0><<<gN2, 256, SMEM>>>(uhi, ulo, whi + O_U_IN, wlo + O_U_IN, bui,
                                         nullptr, nullptr, nullptr, thi, tlo, nullptr,
                                         NN, 256, 256);
        gemm_hmma<2><<<gN1, 256, SMEM>>>(thi, tlo, whi + O_U_OUT, wlo + O_U_OUT, buo,
                                         nullptr, nullptr, h, nullptr, nullptr, h,
                                         NN, 128, 256);
    }
}

// round 7
// speedup vs baseline: 1.6366x; 1.0978x over previous
#include <cuda_runtime.h>
#include <cuda_bf16.h>
#include <math.h>
#include <stdint.h>

#define NN      100000
#define A_AT    150000
#define TROWS   750000
#define SMOOTHF 12.0f
#define MPAD_A  150016   // 1172 * 128
#define MPAD_N  100096   // 782 * 128

// ---------------- scratch (static device globals; no allocations) ----------------
__device__ unsigned short g_xhi[(size_t)MPAD_A * 256];
__device__ unsigned short g_xlo[(size_t)MPAD_A * 256];
__device__ unsigned short g_hhi[(size_t)MPAD_A * 256];
__device__ unsigned short g_hlo[(size_t)MPAD_A * 256];
__device__ float          g_msg[(size_t)TROWS * 128];
__device__ unsigned       g_smaxu[(size_t)NN * 128];
__device__ float          g_smax[(size_t)NN * 128];
__device__ float          g_sum[(size_t)NN * 128];
__device__ unsigned short g_uhi[(size_t)MPAD_N * 256];
__device__ unsigned short g_ulo[(size_t)MPAD_N * 256];
__device__ unsigned short g_thi[(size_t)MPAD_N * 256];
__device__ unsigned short g_tlo[(size_t)MPAD_N * 256];
__device__ unsigned short g_whi[393216];
__device__ unsigned short g_wlo[393216];

// ---------------- helpers ----------------
__device__ __forceinline__ void cp16(void* dst, const void* src) {
    unsigned d = (unsigned)__cvta_generic_to_shared(dst);
    asm volatile("cp.async.cg.shared.global [%0], [%1], 16;" :: "r"(d), "l"(src));
}
#define CP_COMMIT() asm volatile("cp.async.commit_group;")
#define CP_WAIT(n)  asm volatile("cp.async.wait_group %0;" :: "n"(n))

__device__ __forceinline__ void mma_bf16(float* c, const unsigned* a, unsigned b0, unsigned b1) {
    asm volatile("mma.sync.aligned.m16n8k16.row.col.f32.bf16.bf16.f32 "
                 "{%0,%1,%2,%3}, {%4,%5,%6,%7}, {%8,%9}, {%0,%1,%2,%3};"
                 : "+f"(c[0]), "+f"(c[1]), "+f"(c[2]), "+f"(c[3])
                 : "r"(a[0]), "r"(a[1]), "r"(a[2]), "r"(a[3]), "r"(b0), "r"(b1));
}
__device__ __forceinline__ void ldsm4(unsigned* r, unsigned addr) {
    asm volatile("ldmatrix.sync.aligned.m8n8.x4.shared.b16 {%0,%1,%2,%3}, [%4];"
                 : "=r"(r[0]), "=r"(r[1]), "=r"(r[2]), "=r"(r[3]) : "r"(addr));
}
__device__ __forceinline__ unsigned cvt_bf16x2(float hi, float lo) {
    unsigned d; asm("cvt.rn.bf16x2.f32 %0, %1, %2;" : "=r"(d) : "f"(hi), "f"(lo)); return d;
}
__device__ __forceinline__ float bfbits(unsigned u16) { return __uint_as_float(u16 << 16); }

__device__ __forceinline__ float mish_f(float x) {
    float t = __expf(x);
    float u = fmaf(t, t, 2.f * t);
    float r = x * __fdividef(u, u + 2.f);
    return (x > 20.f) ? x : r;
}
__device__ __forceinline__ void split2(float v0, float v1, unsigned& hi, unsigned& lo) {
    unsigned u0 = __float_as_uint(v0), u1 = __float_as_uint(v1);
    hi = (u0 >> 16) | (u1 & 0xFFFF0000u);
    float l0 = v0 - __uint_as_float(u0 & 0xFFFF0000u);
    float l1 = v1 - __uint_as_float(u1 & 0xFFFF0000u);
    lo = cvt_bf16x2(l1, l0);
}
__device__ __forceinline__ unsigned encf(float f) {
    unsigned u = __float_as_uint(f);
    return (u & 0x80000000u) ? ~u : (u | 0x80000000u);
}
__device__ __forceinline__ float decf(unsigned u) {
    return (u & 0x80000000u) ? __uint_as_float(u & 0x7FFFFFFFu) : __uint_as_float(~u);
}

// ---------------- fused weight transpose/split (ONE launch) ----------------
__global__ void convW_all(const float* __restrict__ w0, const float* __restrict__ w1,
                          const float* __restrict__ w2, const float* __restrict__ w3,
                          const float* __restrict__ w4, const float* __restrict__ w5,
                          const float* __restrict__ w6, const float* __restrict__ w7,
                          unsigned short* __restrict__ hi, unsigned short* __restrict__ lo)
{
    int i = blockIdx.x * blockDim.x + threadIdx.x;
    if (i >= 393216) return;
    const float* W; int base, K, N;
    if      (i < 131072) { if (i < 65536)  { W = w0; base = 0;      } else { W = w1; base = 65536;  } K = 256; N = 256; }
    else if (i < 163840) { if (i < 147456) { W = w2; base = 131072; } else { W = w3; base = 147456; } K = 128; N = 128; }
    else if (i < 294912) { if (i < 229376) { W = w4; base = 163840; } else { W = w5; base = 229376; } K = 256; N = 256; }
    else if (i < 360448) { W = w6; base = 294912; K = 256; N = 256; }
    else                 { W = w7; base = 360448; K = 256; N = 128; }
    int li = i - base;
    int k = li / N, n = li - k * N;
    float x = W[li];
    unsigned u = __float_as_uint(x);
    float r = x - __uint_as_float(u & 0xFFFF0000u);
    __nv_bfloat16 lb = __float2bfloat16_rn(r);
    hi[(size_t)base + (size_t)n * K + k] = (unsigned short)(u >> 16);
    lo[(size_t)base + (size_t)n * K + k] = *(unsigned short*)&lb;
}

// ---------------- HMMA GEMM ----------------
// MODE 0: mish -> split bf16 out
// MODE 1: f32 msg out = acc+bias+(Xhi+Xlo), fused atomicMax(segmax) via idx
// MODE 2: f32 out = acc+bias+Xf
#define KC 32
#define STAGE_BYTES 40960
#define OFF_AH 0
#define OFF_AL 10240
#define OFF_BH 20480
#define OFF_BL 30720

template<int MODE>
__global__ void __launch_bounds__(256, 2) gemm_hmma(
    const unsigned short* __restrict__ Ahi, const unsigned short* __restrict__ Alo,
    const unsigned short* __restrict__ Bhi, const unsigned short* __restrict__ Blo,
    const float* __restrict__ bias,
    const unsigned short* __restrict__ Xhi, const unsigned short* __restrict__ Xlo,
    const float* __restrict__ Xf,
    unsigned short* __restrict__ Chi, unsigned short* __restrict__ Clo,
    float* __restrict__ Cf,
    const int* __restrict__ idx, unsigned* __restrict__ smaxG,
    int M, int N, int K)
{
    extern __shared__ char sm[];
    const unsigned sbase = (unsigned)__cvta_generic_to_shared(sm);
    const int tid  = threadIdx.x;
    const int wid  = tid >> 5, lane = tid & 31;
    const int g    = lane >> 2, t = lane & 3;
    const int wm   = wid & 3,  wn = wid >> 2;
    const int row0 = blockIdx.y * 128, col0 = blockIdx.x * 128;
    const int nc   = K >> 5;

    float c[2][8][4];
#pragma unroll
    for (int i = 0; i < 2; i++)
#pragma unroll
        for (int j = 0; j < 8; j++)
#pragma unroll
            for (int q = 0; q < 4; q++) c[i][j][q] = 0.f;

    auto issue = [&](int ch) {
        char* sb = sm + (ch & 1) * STAGE_BYTES;
#pragma unroll
        for (int rep = 0; rep < 2; rep++) {
            int id  = tid + rep * 256;
            int row = id & 127, seg = id >> 7;
            size_t gA = (size_t)(row0 + row) * K + ch * KC + seg * 8;
            size_t gB = (size_t)(col0 + row) * K + ch * KC + seg * 8;
            int so = row * 80 + seg * 16;
            cp16(sb + OFF_AH + so, Ahi + gA);
            cp16(sb + OFF_AL + so, Alo + gA);
            cp16(sb + OFF_BH + so, Bhi + gB);
            cp16(sb + OFF_BL + so, Blo + gB);
        }
    };

    issue(0); CP_COMMIT();

    // ldmatrix lane address components
    const int aRowLane = (lane & 7) + ((lane >> 3) & 1) * 8;   // row within 16-row A tile
    const int aKb      = (lane >> 4) * 16;                     // 0 or 16 bytes (k half)
    const int bRowLane = (lane & 7) + ((lane >> 4) & 1) * 8;   // row within 16-row B pair
    const int bKb      = ((lane >> 3) & 1) * 16;               // 0/16 bytes (b0/b1)

#pragma unroll 1
    for (int ch = 0; ch < nc; ch++) {
        if (ch + 1 < nc) { issue(ch + 1); CP_COMMIT(); CP_WAIT(1); }
        else             { CP_WAIT(0); }
        __syncthreads();
        const unsigned sb = sbase + (ch & 1) * STAGE_BYTES;
#pragma unroll
        for (int ks = 0; ks < 2; ks++) {
            unsigned ah[2][4], al[2][4];
#pragma unroll
            for (int mt = 0; mt < 2; mt++) {
                unsigned arow = (unsigned)(wm * 32 + mt * 16 + aRowLane);
                unsigned aoff = arow * 80 + ks * 32 + aKb;
                ldsm4(ah[mt], sb + OFF_AH + aoff);
                ldsm4(al[mt], sb + OFF_AL + aoff);
            }
#pragma unroll
            for (int p = 0; p < 4; p++) {
                unsigned brow = (unsigned)(wn * 64 + p * 16 + bRowLane);
                unsigned boff = brow * 80 + ks * 32 + bKb;
                unsigned bh[4], bl[4];
                ldsm4(bh, sb + OFF_BH + boff);
                ldsm4(bl, sb + OFF_BL + boff);
#pragma unroll
                for (int mt = 0; mt < 2; mt++) {
                    mma_bf16(c[mt][2 * p],     ah[mt], bh[0], bh[1]);
                    mma_bf16(c[mt][2 * p],     al[mt], bh[0], bh[1]);
                    mma_bf16(c[mt][2 * p],     ah[mt], bl[0], bl[1]);
                    mma_bf16(c[mt][2 * p + 1], ah[mt], bh[2], bh[3]);
                    mma_bf16(c[mt][2 * p + 1], al[mt], bh[2], bh[3]);
                    mma_bf16(c[mt][2 * p + 1], ah[mt], bl[2], bl[3]);
                }
            }
        }
        __syncthreads();
    }

    // ---- epilogue ----
#pragma unroll
    for (int mt = 0; mt < 2; mt++)
#pragma unroll
    for (int half = 0; half < 2; half++) {
        int r = row0 + wm * 32 + mt * 16 + g + half * 8;
        if (r < M) {
#pragma unroll
            for (int nt = 0; nt < 8; nt++) {
                int col = col0 + wn * 64 + nt * 8 + t * 2;
                float v0 = c[mt][nt][half * 2 + 0] + __ldg(bias + col);
                float v1 = c[mt][nt][half * 2 + 1] + __ldg(bias + col + 1);
                size_t idxo = (size_t)r * N + col;
                if (MODE == 0) {
                    v0 = mish_f(v0); v1 = mish_f(v1);
                    unsigned hi, lo;
                    split2(v0, v1, hi, lo);
                    *(unsigned*)(Chi + idxo) = hi;
                    *(unsigned*)(Clo + idxo) = lo;
                } else if (MODE == 1) {
                    unsigned xh = *(const unsigned*)(Xhi + idxo);
                    unsigned xl = *(const unsigned*)(Xlo + idxo);
                    v0 += bfbits(xh & 0xFFFFu) + bfbits(xl & 0xFFFFu);
                    v1 += bfbits(xh >> 16)     + bfbits(xl >> 16);
                    float2 o; o.x = v0; o.y = v1;
                    *(float2*)(Cf + idxo) = o;
                    // fused segment max
                    int node = __ldg(idx + r * (N >> 7) + (col >> 7));
                    unsigned* sp = smaxG + (size_t)node * 128 + (col & 127);
                    atomicMax(sp,     encf(v0));
                    atomicMax(sp + 1, encf(v1));
                } else {
                    float2 x = *(const float2*)(Xf + idxo);
                    float2 o; o.x = v0 + x.x; o.y = v1 + x.y;
                    *(float2*)(Cf + idxo) = o;
                }
            }
        }
    }
}

// ---------------- gather: x[seg] = split(h[av[seg]]) ----------------
__global__ void gather_split(const float* __restrict__ h, const int* __restrict__ av,
                             unsigned short* __restrict__ xhi, unsigned short* __restrict__ xlo,
                             long long nseg)
{
    long long i = (long long)blockIdx.x * blockDim.x + threadIdx.x;
    if (i >= nseg * 32) return;
    long long seg = i >> 5;
    int f4 = (int)(i & 31) * 4;
    int node = __ldg(av + seg);
    float4 v = *(const float4*)(h + (size_t)node * 128 + f4);
    unsigned h01, l01, h23, l23;
    split2(v.x, v.y, h01, l01);
    split2(v.z, v.w, h23, l23);
    *(uint2*)(xhi + seg * 128 + f4) = make_uint2(h01, h23);
    *(uint2*)(xlo + seg * 128 + f4) = make_uint2(l01, l23);
}

// ---------------- aggregation ----------------
__device__ __forceinline__ int row_to_node(long long row, const int* __restrict__ at,
                                           const int* __restrict__ cl, const int* __restrict__ on)
{
    if (row < 300000) return __ldg(at + row);
    if (row < 450000) return __ldg(cl + row - 300000);
    return __ldg(on + row - 450000);
}

__global__ void decode_kernel(const unsigned* __restrict__ smaxu, float* __restrict__ smax,
                              float* __restrict__ sum, long long n)
{
    long long i = (long long)blockIdx.x * blockDim.x + threadIdx.x;
    if (i >= n) return;
    unsigned u = smaxu[i];
    smax[i] = (u == 0u) ? 0.f : decf(u);
    sum[i]  = 0.f;
}

__global__ void expsum_kernel(const float* __restrict__ msg,
                              const int* __restrict__ at, const int* __restrict__ cl,
                              const int* __restrict__ on, const float* __restrict__ smax,
                              float* __restrict__ sum)
{
    long long i = (long long)blockIdx.x * blockDim.x + threadIdx.x;
    if (i >= (long long)TROWS * 32) return;
    long long row = i >> 5;
    int f4 = (int)(i & 31) * 4;
    int node = row_to_node(row, at, cl, on);
    float4 v = *(const float4*)(msg + row * 128 + f4);
    const float4 m = *(const float4*)(smax + (size_t)node * 128 + f4);
    float* p = sum + (size_t)node * 128 + f4;
    atomicAdd(p + 0, __expf(SMOOTHF * (v.x - m.x)));
    atomicAdd(p + 1, __expf(SMOOTHF * (v.y - m.y)));
    atomicAdd(p + 2, __expf(SMOOTHF * (v.z - m.z)));
    atomicAdd(p + 3, __expf(SMOOTHF * (v.w - m.w)));
}

__global__ void updin_kernel(const float* __restrict__ sum, const float* __restrict__ smax,
                             const float* __restrict__ h,
                             unsigned short* __restrict__ uhi, unsigned short* __restrict__ ulo)
{
    long long i = (long long)blockIdx.x * blockDim.x + threadIdx.x;
    if (i >= (long long)NN * 64) return;
    long long node = i >> 6;
    int e = (int)(i & 63) * 2;
    size_t bi = node * 128 + e;
    float m0 = logf(sum[bi] + 1e-16f) / SMOOTHF + smax[bi];
    float m1 = logf(sum[bi + 1] + 1e-16f) / SMOOTHF + smax[bi + 1];
    unsigned hh, ll;
    split2(m0, m1, hh, ll);
    *(unsigned*)(uhi + node * 256 + e) = hh;
    *(unsigned*)(ulo + node * 256 + e) = ll;
    float h0 = h[bi], h1 = h[bi + 1];
    split2(h0, h1, hh, ll);
    *(unsigned*)(uhi + node * 256 + 128 + e) = hh;
    *(unsigned*)(ulo + node * 256 + 128 + e) = ll;
}

// ---------------- host launch ----------------
extern "C" void kernel_launch(void* const* d_in, const int* in_sizes, int n_in,
                              void* d_out, int out_size)
{
    const float *emb, *w_in[3], *b_in[3], *w_out[3], *b_out[3], *wui, *bui, *wuo, *buo;
    const int *at, *cl, *on;

    if (in_sizes[2] == 65536) {
        emb = (const float*)d_in[0];
        at  = (const int*)d_in[1];
        w_in[0] = (const float*)d_in[2];  b_in[0] = (const float*)d_in[3];
        w_out[0] = (const float*)d_in[4]; b_out[0] = (const float*)d_in[5];
        cl  = (const int*)d_in[6];
        w_in[1] = (const float*)d_in[7];  b_in[1] = (const float*)d_in[8];
        w_out[1] = (const float*)d_in[9]; b_out[1] = (const float*)d_in[10];
        on  = (const int*)d_in[11];
        w_in[2] = (const float*)d_in[12];  b_in[2] = (const float*)d_in[13];
        w_out[2] = (const float*)d_in[14]; b_out[2] = (const float*)d_in[15];
        wui = (const float*)d_in[16]; bui = (const float*)d_in[17];
        wuo = (const float*)d_in[18]; buo = (const float*)d_in[19];
    } else {
        emb = (const float*)d_in[0];
        at  = (const int*)d_in[1];
        cl  = (const int*)d_in[2];
        on  = (const int*)d_in[3];
        w_in[0] = (const float*)d_in[4];  b_in[0] = (const float*)d_in[5];
        w_out[0] = (const float*)d_in[6]; b_out[0] = (const float*)d_in[7];
        w_in[1] = (const float*)d_in[8];  b_in[1] = (const float*)d_in[9];
        w_out[1] = (const float*)d_in[10]; b_out[1] = (const float*)d_in[11];
        w_in[2] = (const float*)d_in[12];  b_in[2] = (const float*)d_in[13];
        w_out[2] = (const float*)d_in[14]; b_out[2] = (const float*)d_in[15];
        wui = (const float*)d_in[16]; bui = (const float*)d_in[17];
        wuo = (const float*)d_in[18]; buo = (const float*)d_in[19];
    }

    float* h = (float*)d_out;
    unsigned short *xhi, *xlo, *hhi, *hlo, *uhi, *ulo, *thi, *tlo, *whi, *wlo;
    float *msg, *smaxf, *sum;
    unsigned* smaxu;
    cudaGetSymbolAddress((void**)&xhi, g_xhi);  cudaGetSymbolAddress((void**)&xlo, g_xlo);
    cudaGetSymbolAddress((void**)&hhi, g_hhi);  cudaGetSymbolAddress((void**)&hlo, g_hlo);
    cudaGetSymbolAddress((void**)&uhi, g_uhi);  cudaGetSymbolAddress((void**)&ulo, g_ulo);
    cudaGetSymbolAddress((void**)&thi, g_thi);  cudaGetSymbolAddress((void**)&tlo, g_tlo);
    cudaGetSymbolAddress((void**)&whi, g_whi);  cudaGetSymbolAddress((void**)&wlo, g_wlo);
    cudaGetSymbolAddress((void**)&msg, g_msg);
    cudaGetSymbolAddress((void**)&smaxu, g_smaxu);
    cudaGetSymbolAddress((void**)&smaxf, g_smax);
    cudaGetSymbolAddress((void**)&sum, g_sum);

    const size_t O_AT_IN = 0, O_AT_OUT = 65536, O_CL_IN = 131072, O_CL_OUT = 147456,
                 O_ON_IN = 163840, O_ON_OUT = 229376, O_U_IN = 294912, O_U_OUT = 360448;

    convW_all<<<(393216 + 255) / 256, 256>>>(w_in[0], w_out[0], w_in[1], w_out[1],
                                             w_in[2], w_out[2], wui, wuo, whi, wlo);

    const int SMEM = 2 * STAGE_BYTES;   // 81920
    cudaFuncSetAttribute(gemm_hmma<0>, cudaFuncAttributeMaxDynamicSharedMemorySize, SMEM);
    cudaFuncSetAttribute(gemm_hmma<1>, cudaFuncAttributeMaxDynamicSharedMemorySize, SMEM);
    cudaFuncSetAttribute(gemm_hmma<2>, cudaFuncAttributeMaxDynamicSharedMemorySize, SMEM);

    cudaMemcpyAsync(h, emb, (size_t)NN * 128 * sizeof(float), cudaMemcpyDeviceToDevice);

    const dim3 gA2(2, MPAD_A / 128), gA1(1, MPAD_A / 128);
    const dim3 gN2(2, MPAD_N / 128), gN1(1, MPAD_N / 128);

    for (int layer = 0; layer < 4; layer++) {
        // clear segment-max accumulator before msg GEMMs (their epilogues atomicMax into it)
        cudaMemsetAsync(smaxu, 0, (size_t)NN * 128 * sizeof(unsigned));

        // --- at (ar=2, d=256) -> msg rows [0, 300000) ---
        gather_split<<<(int)((300000LL * 32 + 255) / 256), 256>>>(h, at, xhi, xlo, 300000);
        gemm_hmma<0><<<gA2, 256, SMEM>>>(xhi, xlo, whi + O_AT_IN, wlo + O_AT_IN, b_in[0],
                                         nullptr, nullptr, nullptr, hhi, hlo, nullptr,
                                         nullptr, nullptr, A_AT, 256, 256);
        gemm_hmma<1><<<gA2, 256, SMEM>>>(hhi, hlo, whi + O_AT_OUT, wlo + O_AT_OUT, b_out[0],
                                         xhi, xlo, nullptr, nullptr, nullptr, msg,
                                         at, smaxu, A_AT, 256, 256);

        // --- clear (ar=1, d=128) -> msg rows [300000, 450000) ---
        gather_split<<<(int)((150000LL * 32 + 255) / 256), 256>>>(h, cl, xhi, xlo, 150000);
        gemm_hmma<0><<<gA1, 256, SMEM>>>(xhi, xlo, whi + O_CL_IN, wlo + O_CL_IN, b_in[1],
                                         nullptr, nullptr, nullptr, hhi, hlo, nullptr,
                                         nullptr, nullptr, A_AT, 128, 128);
        gemm_hmma<1><<<gA1, 256, SMEM>>>(hhi, hlo, whi + O_CL_OUT, wlo + O_CL_OUT, b_out[1],
                                         xhi, xlo, nullptr, nullptr, nullptr,
                                         msg + (size_t)300000 * 128, cl, smaxu, A_AT, 128, 128);

        // --- on (ar=2, d=256) -> msg rows [450000, 750000) ---
        gather_split<<<(int)((300000LL * 32 + 255) / 256), 256>>>(h, on, xhi, xlo, 300000);
        gemm_hmma<0><<<gA2, 256, SMEM>>>(xhi, xlo, whi + O_ON_IN, wlo + O_ON_IN, b_in[2],
                                         nullptr, nullptr, nullptr, hhi, hlo, nullptr,
                                         nullptr, nullptr, A_AT, 256, 256);
        gemm_hmma<1><<<gA2, 256, SMEM>>>(hhi, hlo, whi + O_ON_OUT, wlo + O_ON_OUT, b_out[2],
                                         xhi, xlo, nullptr, nullptr, nullptr,
                                         msg + (size_t)450000 * 128, on, smaxu, A_AT, 256, 256);

        // --- smooth-max aggregation (segmax already fused into GEMM epilogues) ---
        decode_kernel<<<(int)(((long long)NN * 128 + 255) / 256), 256>>>(smaxu, smaxf, sum,
                                                                         (long long)NN * 128);
        expsum_kernel<<<(int)(((long long)TROWS * 32 + 255) / 256), 256>>>(msg, at, cl, on,
                                                                           smaxf, sum);
        updin_kernel<<<(int)(((long long)NN * 64 + 255) / 256), 256>>>(sum, smaxf, h, uhi, ulo);

        // --- node update MLP + outer residual (h in place) ---
        gemm_hmma<0><<<gN2, 256, SMEM>>>(uhi, ulo, whi + O_U_IN, wlo + O_U_IN, bui,
                                         nullptr, nullptr, nullptr, thi, tlo, nullptr,
                                         nullptr, nullptr, NN, 256, 256);
        gemm_hmma<2><<<gN1, 256, SMEM>>>(thi, tlo, whi + O_U_OUT, wlo + O_U_OUT, buo,
                                         nullptr, nullptr, h, nullptr, nullptr, h,
                                         nullptr, nullptr, NN, 128, 256);
    }
}

// round 8
// speedup vs baseline: 1.9128x; 1.1687x over previous
#include <cuda_runtime.h>
#include <cuda_bf16.h>
#include <math.h>
#include <stdint.h>

#define NN      100000
#define A_AT    150000
#define TROWS   750000
#define SMOOTHF 12.0f
#define MPAD_A  150016   // 2344 * 64
#define MPAD_N  100096   // 1564 * 64

// ---------------- scratch (static device globals; no allocations) ----------------
__device__ unsigned short g_xhi[(size_t)MPAD_A * 256];
__device__ unsigned short g_xlo[(size_t)MPAD_A * 256];
__device__ unsigned short g_hhi[(size_t)MPAD_A * 256];
__device__ unsigned short g_hlo[(size_t)MPAD_A * 256];
__device__ float          g_msg[(size_t)TROWS * 128];
__device__ unsigned       g_smaxu[(size_t)NN * 128];
__device__ float          g_smax[(size_t)NN * 128];
__device__ float          g_sum[(size_t)NN * 128];
__device__ unsigned short g_uhi[(size_t)MPAD_N * 256];
__device__ unsigned short g_ulo[(size_t)MPAD_N * 256];
__device__ unsigned short g_thi[(size_t)MPAD_N * 256];
__device__ unsigned short g_tlo[(size_t)MPAD_N * 256];
__device__ unsigned short g_whi[393216];
__device__ unsigned short g_wlo[393216];

// ---------------- helpers ----------------
__device__ __forceinline__ void cp16(void* dst, const void* src) {
    unsigned d = (unsigned)__cvta_generic_to_shared(dst);
    asm volatile("cp.async.cg.shared.global [%0], [%1], 16;" :: "r"(d), "l"(src));
}
#define CP_COMMIT() asm volatile("cp.async.commit_group;")
#define CP_WAIT(n)  asm volatile("cp.async.wait_group %0;" :: "n"(n))

__device__ __forceinline__ void mma_bf16(float* c, const unsigned* a, unsigned b0, unsigned b1) {
    asm volatile("mma.sync.aligned.m16n8k16.row.col.f32.bf16.bf16.f32 "
                 "{%0,%1,%2,%3}, {%4,%5,%6,%7}, {%8,%9}, {%0,%1,%2,%3};"
                 : "+f"(c[0]), "+f"(c[1]), "+f"(c[2]), "+f"(c[3])
                 : "r"(a[0]), "r"(a[1]), "r"(a[2]), "r"(a[3]), "r"(b0), "r"(b1));
}
__device__ __forceinline__ void ldsm4(unsigned* r, unsigned addr) {
    asm volatile("ldmatrix.sync.aligned.m8n8.x4.shared.b16 {%0,%1,%2,%3}, [%4];"
                 : "=r"(r[0]), "=r"(r[1]), "=r"(r[2]), "=r"(r[3]) : "r"(addr));
}
__device__ __forceinline__ unsigned cvt_bf16x2(float hi, float lo) {
    unsigned d; asm("cvt.rn.bf16x2.f32 %0, %1, %2;" : "=r"(d) : "f"(hi), "f"(lo)); return d;
}
__device__ __forceinline__ float bfbits(unsigned u16) { return __uint_as_float(u16 << 16); }

__device__ __forceinline__ float mish_f(float x) {
    float t = __expf(x);
    float u = fmaf(t, t, 2.f * t);
    float r = x * __fdividef(u, u + 2.f);
    return (x > 20.f) ? x : r;
}
__device__ __forceinline__ void split2(float v0, float v1, unsigned& hi, unsigned& lo) {
    unsigned u0 = __float_as_uint(v0), u1 = __float_as_uint(v1);
    hi = (u0 >> 16) | (u1 & 0xFFFF0000u);
    float l0 = v0 - __uint_as_float(u0 & 0xFFFF0000u);
    float l1 = v1 - __uint_as_float(u1 & 0xFFFF0000u);
    lo = cvt_bf16x2(l1, l0);
}
__device__ __forceinline__ unsigned encf(float f) {
    unsigned u = __float_as_uint(f);
    return (u & 0x80000000u) ? ~u : (u | 0x80000000u);
}
__device__ __forceinline__ float decf(unsigned u) {
    return (u & 0x80000000u) ? __uint_as_float(u & 0x7FFFFFFFu) : __uint_as_float(~u);
}

// ---------------- fused weight transpose/split (ONE launch) ----------------
__global__ void convW_all(const float* __restrict__ w0, const float* __restrict__ w1,
                          const float* __restrict__ w2, const float* __restrict__ w3,
                          const float* __restrict__ w4, const float* __restrict__ w5,
                          const float* __restrict__ w6, const float* __restrict__ w7,
                          unsigned short* __restrict__ hi, unsigned short* __restrict__ lo)
{
    int i = blockIdx.x * blockDim.x + threadIdx.x;
    if (i >= 393216) return;
    const float* W; int base, K, N;
    if      (i < 131072) { if (i < 65536)  { W = w0; base = 0;      } else { W = w1; base = 65536;  } K = 256; N = 256; }
    else if (i < 163840) { if (i < 147456) { W = w2; base = 131072; } else { W = w3; base = 147456; } K = 128; N = 128; }
    else if (i < 294912) { if (i < 229376) { W = w4; base = 163840; } else { W = w5; base = 229376; } K = 256; N = 256; }
    else if (i < 360448) { W = w6; base = 294912; K = 256; N = 256; }
    else                 { W = w7; base = 360448; K = 256; N = 128; }
    int li = i - base;
    int k = li / N, n = li - k * N;
    float x = W[li];
    unsigned u = __float_as_uint(x);
    float r = x - __uint_as_float(u & 0xFFFF0000u);
    __nv_bfloat16 lb = __float2bfloat16_rn(r);
    hi[(size_t)base + (size_t)n * K + k] = (unsigned short)(u >> 16);
    lo[(size_t)base + (size_t)n * K + k] = *(unsigned short*)&lb;
}

// ---------------- HMMA GEMM, CTA tile 64x128, 3 CTAs/SM ----------------
// MODE 0: mish -> split bf16 out
// MODE 1: f32 msg out = acc+bias+(Xhi+Xlo), fused atomicMax(segmax) via idx
// MODE 2: f32 out = acc+bias+Xf
#define KC 32
#define STAGE_BYTES 30720
#define OFF_AH 0
#define OFF_AL 5120
#define OFF_BH 10240
#define OFF_BL 20480

template<int MODE>
__global__ void __launch_bounds__(256, 3) gemm_hmma(
    const unsigned short* __restrict__ Ahi, const unsigned short* __restrict__ Alo,
    const unsigned short* __restrict__ Bhi, const unsigned short* __restrict__ Blo,
    const float* __restrict__ bias,
    const unsigned short* __restrict__ Xhi, const unsigned short* __restrict__ Xlo,
    const float* __restrict__ Xf,
    unsigned short* __restrict__ Chi, unsigned short* __restrict__ Clo,
    float* __restrict__ Cf,
    const int* __restrict__ idx, unsigned* __restrict__ smaxG,
    int M, int N, int K)
{
    extern __shared__ char sm[];
    const unsigned sbase = (unsigned)__cvta_generic_to_shared(sm);
    const int tid  = threadIdx.x;
    const int wid  = tid >> 5, lane = tid & 31;
    const int g    = lane >> 2, t = lane & 3;
    const int wm   = wid & 1,  wn = wid >> 1;       // 2 x 4 warp grid, warp tile 32x32
    const int row0 = blockIdx.y * 64, col0 = blockIdx.x * 128;
    const int nc   = K >> 5;

    float c[2][4][4];
#pragma unroll
    for (int i = 0; i < 2; i++)
#pragma unroll
        for (int j = 0; j < 4; j++)
#pragma unroll
            for (int q = 0; q < 4; q++) c[i][j][q] = 0.f;

    auto issue = [&](int ch) {
        char* sb = sm + (ch & 1) * STAGE_BYTES;
        // B: 128 rows x 4 quads, hi+lo  (2 reps x 256 threads)
#pragma unroll
        for (int rep = 0; rep < 2; rep++) {
            int id  = tid + rep * 256;
            int row = id >> 2, q = id & 3;
            size_t gB = (size_t)(col0 + row) * K + ch * KC + q * 8;
            int so = row * 80 + q * 16;
            cp16(sb + OFF_BH + so, Bhi + gB);
            cp16(sb + OFF_BL + so, Blo + gB);
        }
        // A: 64 rows x 4 quads, hi+lo (256 threads exactly)
        {
            int row = tid >> 2, q = tid & 3;
            size_t gA = (size_t)(row0 + row) * K + ch * KC + q * 8;
            int so = row * 80 + q * 16;
            cp16(sb + OFF_AH + so, Ahi + gA);
            cp16(sb + OFF_AL + so, Alo + gA);
        }
    };

    issue(0); CP_COMMIT();

    const int aRowLane = (lane & 7) + ((lane >> 3) & 1) * 8;
    const int aKb      = (lane >> 4) * 16;
    const int bRowLane = (lane & 7) + ((lane >> 4) & 1) * 8;
    const int bKb      = ((lane >> 3) & 1) * 16;

#pragma unroll 1
    for (int ch = 0; ch < nc; ch++) {
        if (ch + 1 < nc) { issue(ch + 1); CP_COMMIT(); CP_WAIT(1); }
        else             { CP_WAIT(0); }
        __syncthreads();
        const unsigned sb = sbase + (ch & 1) * STAGE_BYTES;
#pragma unroll
        for (int ks = 0; ks < 2; ks++) {
            unsigned ah[2][4], al[2][4];
#pragma unroll
            for (int mt = 0; mt < 2; mt++) {
                unsigned arow = (unsigned)(wm * 32 + mt * 16 + aRowLane);
                unsigned aoff = arow * 80 + ks * 32 + aKb;
                ldsm4(ah[mt], sb + OFF_AH + aoff);
                ldsm4(al[mt], sb + OFF_AL + aoff);
            }
#pragma unroll
            for (int p = 0; p < 2; p++) {
                unsigned brow = (unsigned)(wn * 32 + p * 16 + bRowLane);
                unsigned boff = brow * 80 + ks * 32 + bKb;
                unsigned bh[4], bl[4];
                ldsm4(bh, sb + OFF_BH + boff);
                ldsm4(bl, sb + OFF_BL + boff);
#pragma unroll
                for (int mt = 0; mt < 2; mt++) {
                    mma_bf16(c[mt][2 * p],     ah[mt], bh[0], bh[1]);
                    mma_bf16(c[mt][2 * p],     al[mt], bh[0], bh[1]);
                    mma_bf16(c[mt][2 * p],     ah[mt], bl[0], bl[1]);
                    mma_bf16(c[mt][2 * p + 1], ah[mt], bh[2], bh[3]);
                    mma_bf16(c[mt][2 * p + 1], al[mt], bh[2], bh[3]);
                    mma_bf16(c[mt][2 * p + 1], ah[mt], bl[2], bl[3]);
                }
            }
        }
        __syncthreads();
    }

    // ---- epilogue ----
#pragma unroll
    for (int mt = 0; mt < 2; mt++)
#pragma unroll
    for (int half = 0; half < 2; half++) {
        int r = row0 + wm * 32 + mt * 16 + g + half * 8;
        if (r < M) {
#pragma unroll
            for (int nt = 0; nt < 4; nt++) {
                int col = col0 + wn * 32 + nt * 8 + t * 2;
                float v0 = c[mt][nt][half * 2 + 0] + __ldg(bias + col);
                float v1 = c[mt][nt][half * 2 + 1] + __ldg(bias + col + 1);
                size_t idxo = (size_t)r * N + col;
                if (MODE == 0) {
                    v0 = mish_f(v0); v1 = mish_f(v1);
                    unsigned hi, lo;
                    split2(v0, v1, hi, lo);
                    *(unsigned*)(Chi + idxo) = hi;
                    *(unsigned*)(Clo + idxo) = lo;
                } else if (MODE == 1) {
                    unsigned xh = *(const unsigned*)(Xhi + idxo);
                    unsigned xl = *(const unsigned*)(Xlo + idxo);
                    v0 += bfbits(xh & 0xFFFFu) + bfbits(xl & 0xFFFFu);
                    v1 += bfbits(xh >> 16)     + bfbits(xl >> 16);
                    float2 o; o.x = v0; o.y = v1;
                    *(float2*)(Cf + idxo) = o;
                    int node = __ldg(idx + r * (N >> 7) + (col >> 7));
                    unsigned* sp = smaxG + (size_t)node * 128 + (col & 127);
                    atomicMax(sp,     encf(v0));
                    atomicMax(sp + 1, encf(v1));
                } else {
                    float2 x = *(const float2*)(Xf + idxo);
                    float2 o; o.x = v0 + x.x; o.y = v1 + x.y;
                    *(float2*)(Cf + idxo) = o;
                }
            }
        }
    }
}

// ---------------- gather: x[seg] = split(h[av[seg]]) ----------------
__global__ void gather_split(const float* __restrict__ h, const int* __restrict__ av,
                             unsigned short* __restrict__ xhi, unsigned short* __restrict__ xlo,
                             long long nseg)
{
    long long i = (long long)blockIdx.x * blockDim.x + threadIdx.x;
    if (i >= nseg * 32) return;
    long long seg = i >> 5;
    int f4 = (int)(i & 31) * 4;
    int node = __ldg(av + seg);
    float4 v = *(const float4*)(h + (size_t)node * 128 + f4);
    unsigned h01, l01, h23, l23;
    split2(v.x, v.y, h01, l01);
    split2(v.z, v.w, h23, l23);
    *(uint2*)(xhi + seg * 128 + f4) = make_uint2(h01, h23);
    *(uint2*)(xlo + seg * 128 + f4) = make_uint2(l01, l23);
}

// ---------------- aggregation ----------------
__device__ __forceinline__ int row_to_node(long long row, const int* __restrict__ at,
                                           const int* __restrict__ cl, const int* __restrict__ on)
{
    if (row < 300000) return __ldg(at + row);
    if (row < 450000) return __ldg(cl + row - 300000);
    return __ldg(on + row - 450000);
}

__global__ void decode_kernel(const unsigned* __restrict__ smaxu, float* __restrict__ smax,
                              float* __restrict__ sum, long long n)
{
    long long i = (long long)blockIdx.x * blockDim.x + threadIdx.x;
    if (i >= n) return;
    unsigned u = smaxu[i];
    smax[i] = (u == 0u) ? 0.f : decf(u);
    sum[i]  = 0.f;
}

__global__ void expsum_kernel(const float* __restrict__ msg,
                              const int* __restrict__ at, const int* __restrict__ cl,
                              const int* __restrict__ on, const float* __restrict__ smax,
                              float* __restrict__ sum)
{
    long long i = (long long)blockIdx.x * blockDim.x + threadIdx.x;
    if (i >= (long long)TROWS * 32) return;
    long long row = i >> 5;
    int f4 = (int)(i & 31) * 4;
    int node = row_to_node(row, at, cl, on);
    float4 v = *(const float4*)(msg + row * 128 + f4);
    const float4 m = *(const float4*)(smax + (size_t)node * 128 + f4);
    float* p = sum + (size_t)node * 128 + f4;
    atomicAdd(p + 0, __expf(SMOOTHF * (v.x - m.x)));
    atomicAdd(p + 1, __expf(SMOOTHF * (v.y - m.y)));
    atomicAdd(p + 2, __expf(SMOOTHF * (v.z - m.z)));
    atomicAdd(p + 3, __expf(SMOOTHF * (v.w - m.w)));
}

__global__ void updin_kernel(const float* __restrict__ sum, const float* __restrict__ smax,
                             const float* __restrict__ h,
                             unsigned short* __restrict__ uhi, unsigned short* __restrict__ ulo)
{
    long long i = (long long)blockIdx.x * blockDim.x + threadIdx.x;
    if (i >= (long long)NN * 64) return;
    long long node = i >> 6;
    int e = (int)(i & 63) * 2;
    size_t bi = node * 128 + e;
    float m0 = logf(sum[bi] + 1e-16f) / SMOOTHF + smax[bi];
    float m1 = logf(sum[bi + 1] + 1e-16f) / SMOOTHF + smax[bi + 1];
    unsigned hh, ll;
    split2(m0, m1, hh, ll);
    *(unsigned*)(uhi + node * 256 + e) = hh;
    *(unsigned*)(ulo + node * 256 + e) = ll;
    float h0 = h[bi], h1 = h[bi + 1];
    split2(h0, h1, hh, ll);
    *(unsigned*)(uhi + node * 256 + 128 + e) = hh;
    *(unsigned*)(ulo + node * 256 + 128 + e) = ll;
}

// ---------------- host launch ----------------
extern "C" void kernel_launch(void* const* d_in, const int* in_sizes, int n_in,
                              void* d_out, int out_size)
{
    const float *emb, *w_in[3], *b_in[3], *w_out[3], *b_out[3], *wui, *bui, *wuo, *buo;
    const int *at, *cl, *on;

    if (in_sizes[2] == 65536) {
        emb = (const float*)d_in[0];
        at  = (const int*)d_in[1];
        w_in[0] = (const float*)d_in[2];  b_in[0] = (const float*)d_in[3];
        w_out[0] = (const float*)d_in[4]; b_out[0] = (const float*)d_in[5];
        cl  = (const int*)d_in[6];
        w_in[1] = (const float*)d_in[7];  b_in[1] = (const float*)d_in[8];
        w_out[1] = (const float*)d_in[9]; b_out[1] = (const float*)d_in[10];
        on  = (const int*)d_in[11];
        w_in[2] = (const float*)d_in[12];  b_in[2] = (const float*)d_in[13];
        w_out[2] = (const float*)d_in[14]; b_out[2] = (const float*)d_in[15];
        wui = (const float*)d_in[16]; bui = (const float*)d_in[17];
        wuo = (const float*)d_in[18]; buo = (const float*)d_in[19];
    } else {
        emb = (const float*)d_in[0];
        at  = (const int*)d_in[1];
        cl  = (const int*)d_in[2];
        on  = (const int*)d_in[3];
        w_in[0] = (const float*)d_in[4];  b_in[0] = (const float*)d_in[5];
        w_out[0] = (const float*)d_in[6]; b_out[0] = (const float*)d_in[7];
        w_in[1] = (const float*)d_in[8];  b_in[1] = (const float*)d_in[9];
        w_out[1] = (const float*)d_in[10]; b_out[1] = (const float*)d_in[11];
        w_in[2] = (const float*)d_in[12];  b_in[2] = (const float*)d_in[13];
        w_out[2] = (const float*)d_in[14]; b_out[2] = (const float*)d_in[15];
        wui = (const float*)d_in[16]; bui = (const float*)d_in[17];
        wuo = (const float*)d_in[18]; buo = (const float*)d_in[19];
    }

    float* h = (float*)d_out;
    unsigned short *xhi, *xlo, *hhi, *hlo, *uhi, *ulo, *thi, *tlo, *whi, *wlo;
    float *msg, *smaxf, *sum;
    unsigned* smaxu;
    cudaGetSymbolAddress((void**)&xhi, g_xhi);  cudaGetSymbolAddress((void**)&xlo, g_xlo);
    cudaGetSymbolAddress((void**)&hhi, g_hhi);  cudaGetSymbolAddress((void**)&hlo, g_hlo);
    cudaGetSymbolAddress((void**)&uhi, g_uhi);  cudaGetSymbolAddress((void**)&ulo, g_ulo);
    cudaGetSymbolAddress((void**)&thi, g_thi);  cudaGetSymbolAddress((void**)&tlo, g_tlo);
    cudaGetSymbolAddress((void**)&whi, g_whi);  cudaGetSymbolAddress((void**)&wlo, g_wlo);
    cudaGetSymbolAddress((void**)&msg, g_msg);
    cudaGetSymbolAddress((void**)&smaxu, g_smaxu);
    cudaGetSymbolAddress((void**)&smaxf, g_smax);
    cudaGetSymbolAddress((void**)&sum, g_sum);

    const size_t O_AT_IN = 0, O_AT_OUT = 65536, O_CL_IN = 131072, O_CL_OUT = 147456,
                 O_ON_IN = 163840, O_ON_OUT = 229376, O_U_IN = 294912, O_U_OUT = 360448;

    convW_all<<<(393216 + 255) / 256, 256>>>(w_in[0], w_out[0], w_in[1], w_out[1],
                                             w_in[2], w_out[2], wui, wuo, whi, wlo);

    const int SMEM = 2 * STAGE_BYTES;   // 61440
    cudaFuncSetAttribute(gemm_hmma<0>, cudaFuncAttributeMaxDynamicSharedMemorySize, SMEM);
    cudaFuncSetAttribute(gemm_hmma<1>, cudaFuncAttributeMaxDynamicSharedMemorySize, SMEM);
    cudaFuncSetAttribute(gemm_hmma<2>, cudaFuncAttributeMaxDynamicSharedMemorySize, SMEM);

    cudaMemcpyAsync(h, emb, (size_t)NN * 128 * sizeof(float), cudaMemcpyDeviceToDevice);

    const dim3 gA2(2, MPAD_A / 64), gA1(1, MPAD_A / 64);
    const dim3 gN2(2, MPAD_N / 64), gN1(1, MPAD_N / 64);

    for (int layer = 0; layer < 4; layer++) {
        cudaMemsetAsync(smaxu, 0, (size_t)NN * 128 * sizeof(unsigned));

        // --- at (ar=2, d=256) -> msg rows [0, 300000) ---
        gather_split<<<(int)((300000LL * 32 + 255) / 256), 256>>>(h, at, xhi, xlo, 300000);
        gemm_hmma<0><<<gA2, 256, SMEM>>>(xhi, xlo, whi + O_AT_IN, wlo + O_AT_IN, b_in[0],
                                         nullptr, nullptr, nullptr, hhi, hlo, nullptr,
                                         nullptr, nullptr, A_AT, 256, 256);
        gemm_hmma<1><<<gA2, 256, SMEM>>>(hhi, hlo, whi + O_AT_OUT, wlo + O_AT_OUT, b_out[0],
                                         xhi, xlo, nullptr, nullptr, nullptr, msg,
                                         at, smaxu, A_AT, 256, 256);

        // --- clear (ar=1, d=128) -> msg rows [300000, 450000) ---
        gather_split<<<(int)((150000LL * 32 + 255) / 256), 256>>>(h, cl, xhi, xlo, 150000);
        gemm_hmma<0><<<gA1, 256, SMEM>>>(xhi, xlo, whi + O_CL_IN, wlo + O_CL_IN, b_in[1],
                                         nullptr, nullptr, nullptr, hhi, hlo, nullptr,
                                         nullptr, nullptr, A_AT, 128, 128);
        gemm_hmma<1><<<gA1, 256, SMEM>>>(hhi, hlo, whi + O_CL_OUT, wlo + O_CL_OUT, b_out[1],
                                         xhi, xlo, nullptr, nullptr, nullptr,
                                         msg + (size_t)300000 * 128, cl, smaxu, A_AT, 128, 128);

        // --- on (ar=2, d=256) -> msg rows [450000, 750000) ---
        gather_split<<<(int)((300000LL * 32 + 255) / 256), 256>>>(h, on, xhi, xlo, 300000);
        gemm_hmma<0><<<gA2, 256, SMEM>>>(xhi, xlo, whi + O_ON_IN, wlo + O_ON_IN, b_in[2],
                                         nullptr, nullptr, nullptr, hhi, hlo, nullptr,
                                         nullptr, nullptr, A_AT, 256, 256);
        gemm_hmma<1><<<gA2, 256, SMEM>>>(hhi, hlo, whi + O_ON_OUT, wlo + O_ON_OUT, b_out[2],
                                         xhi, xlo, nullptr, nullptr, nullptr,
                                         msg + (size_t)450000 * 128, on, smaxu, A_AT, 256, 256);

        // --- smooth-max aggregation (segmax fused into GEMM epilogues) ---
        decode_kernel<<<(int)(((long long)NN * 128 + 255) / 256), 256>>>(smaxu, smaxf, sum,
                                                                         (long long)NN * 128);
        expsum_kernel<<<(int)(((long long)TROWS * 32 + 255) / 256), 256>>>(msg, at, cl, on,
                                                                           smaxf, sum);
        updin_kernel<<<(int)(((long long)NN * 64 + 255) / 256), 256>>>(sum, smaxf, h, uhi, ulo);

        // --- node update MLP + outer residual (h in place) ---
        gemm_hmma<0><<<gN2, 256, SMEM>>>(uhi, ulo, whi + O_U_IN, wlo + O_U_IN, bui,
                                         nullptr, nullptr, nullptr, thi, tlo, nullptr,
                                         nullptr, nullptr, NN, 256, 256);
        gemm_hmma<2><<<gN1, 256, SMEM>>>(thi, tlo, whi + O_U_OUT, wlo + O_U_OUT, buo,
                                         nullptr, nullptr, h, nullptr, nullptr, h,
                                         nullptr, nullptr, NN, 128, 256);
    }
}